// round 2
// baseline (speedup 1.0000x reference)
#include <cuda_runtime.h>
#include <math.h>

#define NN 20000
#define EE 200000
#define ND 64
#define ED 32
#define GD 32
#define HD 128
#define DOF 6
#define PI_F 3.14159265358979f

#define K1   172   // edge MLP input width (even -> 86 k-pairs)
#define FSTR 172   // smem stride of feature tile (172*4 B = 16B-multiple)
#define HSTR 128   // smem stride of hidden tile
#define K3   224   // node MLP input width
#define GSTR 224
#define NHSTR 132  // node kernel hidden stride (legacy)

typedef unsigned long long ull;

// scratch accumulators (no cudaMalloc allowed)
__device__ float g_sums[NN * HD];
__device__ float g_cnt[NN];

__global__ void zero_kernel() {
    int idx = blockIdx.x * blockDim.x + threadIdx.x;
    if (idx < NN * HD / 4) ((float4*)g_sums)[idx] = make_float4(0.f, 0.f, 0.f, 0.f);
    if (idx < NN)          g_cnt[idx] = 0.0f;
}

__device__ __forceinline__ ull fma2(ull a, ull b, ull c) {
    ull d;
    asm("fma.rn.f32x2 %0, %1, %2, %3;" : "=l"(d) : "l"(a), "l"(b), "l"(c));
    return d;
}
__device__ __forceinline__ ull pack2(float lo, float hi) {
    ull d;
    asm("mov.b64 %0, {%1, %2};" : "=l"(d) : "f"(lo), "f"(hi));
    return d;
}
__device__ __forceinline__ float merge2(ull v) {
    float lo, hi;
    asm("mov.b64 {%0, %1}, %2;" : "=f"(lo), "=f"(hi) : "l"(v));
    return lo + hi;
}

// ---------------- Edge kernel: 32 edges (64 feature rows) per block ----------------
// 8 warps: warp owns rows warp*8..warp*8+7; lane owns cols lane*4..lane*4+3.
// K packed in pairs via fma.rn.f32x2; W read directly from global (L1-resident,
// 1 block/SM forced by smem padding so the 88KB W1 fits the L1D carveout).
__global__ __launch_bounds__(256, 1)
void edge_kernel(const float* __restrict__ xfeat, const float* __restrict__ T_R,
                 const float* __restrict__ T_t,  const float* __restrict__ edge_feat,
                 const float* __restrict__ TijR, const float* __restrict__ Tijt,
                 const int* __restrict__ ei,
                 const float* __restrict__ W1, const float* __restrict__ b1,
                 const float* __restrict__ W2, const float* __restrict__ b2)
{
    extern __shared__ float sm[];
    float* sF = sm;                  // 64 x FSTR
    float* sH = sF + 64 * FSTR;      // 64 x HSTR
    __shared__ int sNode[64];

    int tid = threadIdx.x;
    int e0 = blockIdx.x * 32;

    // ---- feature copy: xfeat_i, xfeat_j, edge_feat ----
    {
        int sub = tid & 7;
        int el  = tid >> 3;              // local edge 0..31
        int e   = e0 + el;
        int vi = ei[e], vj = ei[EE + e];
        const float4* xi4 = (const float4*)(xfeat + vi * ND);
        const float4* xj4 = (const float4*)(xfeat + vj * ND);
        const float4* ef4 = (const float4*)(edge_feat + e * ED);
        float* rowA = sF + el * FSTR;          // f_ij
        float* rowB = sF + (32 + el) * FSTR;   // f_ji
        #pragma unroll
        for (int q = sub; q < 16; q += 8) {
            float4 v = xi4[q];
            *(float4*)(rowA + q * 4)       = v;
            *(float4*)(rowB + 64 + q * 4)  = v;
            float4 w = xj4[q];
            *(float4*)(rowA + 64 + q * 4)  = w;
            *(float4*)(rowB + q * 4)       = w;
        }
        float4 v = ef4[sub];
        *(float4*)(rowA + 128 + sub * 4) = v;
        *(float4*)(rowB + 128 + sub * 4) = v;
    }

    // ---- relative pose features (1 thread per edge) ----
    if (tid < 32) {
        int e = e0 + tid;
        int vi = ei[e], vj = ei[EE + e];
        sNode[tid]      = vj;   // f_ij aggregates into j
        sNode[32 + tid] = vi;   // f_ji aggregates into i
        float Ri[9], Rj[9], Tr[9], ti[3], tj[3], tt[3];
        #pragma unroll
        for (int k = 0; k < 9; k++) { Ri[k] = T_R[vi*9+k]; Rj[k] = T_R[vj*9+k]; Tr[k] = TijR[e*9+k]; }
        #pragma unroll
        for (int k = 0; k < 3; k++) { ti[k] = T_t[vi*3+k]; tj[k] = T_t[vj*3+k]; tt[k] = Tijt[e*3+k]; }
        float A[9], ta[3];
        #pragma unroll
        for (int r = 0; r < 3; r++)
            #pragma unroll
            for (int c = 0; c < 3; c++)
                A[r*3+c] = Rj[r*3+0]*Ri[c*3+0] + Rj[r*3+1]*Ri[c*3+1] + Rj[r*3+2]*Ri[c*3+2];
        #pragma unroll
        for (int r = 0; r < 3; r++)
            ta[r] = tj[r] - (A[r*3+0]*ti[0] + A[r*3+1]*ti[1] + A[r*3+2]*ti[2]);
        float Re[9], te[3];
        #pragma unroll
        for (int r = 0; r < 3; r++)
            #pragma unroll
            for (int c = 0; c < 3; c++)
                Re[r*3+c] = A[r*3+0]*Tr[c*3+0] + A[r*3+1]*Tr[c*3+1] + A[r*3+2]*Tr[c*3+2];
        #pragma unroll
        for (int r = 0; r < 3; r++)
            te[r] = ta[r] - (Re[r*3+0]*tt[0] + Re[r*3+1]*tt[1] + Re[r*3+2]*tt[2]);
        float* fA = sF + tid * FSTR + 160;
        fA[0]=Re[0]; fA[1]=Re[1]; fA[2]=Re[2];  fA[3]=te[0];
        fA[4]=Re[3]; fA[5]=Re[4]; fA[6]=Re[5];  fA[7]=te[1];
        fA[8]=Re[6]; fA[9]=Re[7]; fA[10]=Re[8]; fA[11]=te[2];
        float tb[3], Rf[9], tf[3];
        #pragma unroll
        for (int r = 0; r < 3; r++)
            tb[r] = ti[r] - (A[0+r]*tj[0] + A[3+r]*tj[1] + A[6+r]*tj[2]);
        #pragma unroll
        for (int r = 0; r < 3; r++)
            #pragma unroll
            for (int c = 0; c < 3; c++)
                Rf[r*3+c] = A[0+r]*Tr[0+c] + A[3+r]*Tr[3+c] + A[6+r]*Tr[6+c];
        #pragma unroll
        for (int r = 0; r < 3; r++)
            tf[r] = tb[r] + (A[0+r]*tt[0] + A[3+r]*tt[1] + A[6+r]*tt[2]);
        float* fB = sF + (32 + tid) * FSTR + 160;
        fB[0]=Rf[0]; fB[1]=Rf[1]; fB[2]=Rf[2];  fB[3]=tf[0];
        fB[4]=Rf[3]; fB[5]=Rf[4]; fB[6]=Rf[5];  fB[7]=tf[1];
        fB[8]=Rf[6]; fB[9]=Rf[7]; fB[10]=Rf[8]; fB[11]=tf[2];
    }
    __syncthreads();

    int warp = tid >> 5, lane = tid & 31;
    const float* fbase = sF + (warp * 8) * FSTR;

    // ---- GEMM1: 64 x 172 @ 172 x 128, K packed in pairs ----
    ull acc[8][4];
    #pragma unroll
    for (int i = 0; i < 8; i++)
        #pragma unroll
        for (int c = 0; c < 4; c++) acc[i][c] = 0ull;

    {
        const float4* Wv = (const float4*)W1 + lane;
        #pragma unroll 2
        for (int p = 0; p < K1 / 2; p++) {
            int k = 2 * p;
            float4 w0 = Wv[(size_t)k * 32];
            float4 w1 = Wv[(size_t)(k + 1) * 32];
            ull wx = pack2(w0.x, w1.x);
            ull wy = pack2(w0.y, w1.y);
            ull wz = pack2(w0.z, w1.z);
            ull ww = pack2(w0.w, w1.w);
            #pragma unroll
            for (int i = 0; i < 8; i++) {
                ull a = *(const ull*)(fbase + i * FSTR + k);
                acc[i][0] = fma2(a, wx, acc[i][0]);
                acc[i][1] = fma2(a, wy, acc[i][1]);
                acc[i][2] = fma2(a, wz, acc[i][2]);
                acc[i][3] = fma2(a, ww, acc[i][3]);
            }
        }
    }

    // bias + relu -> sH (warp-private rows; no block barrier needed)
    {
        float4 bv = ((const float4*)b1)[lane];
        #pragma unroll
        for (int i = 0; i < 8; i++) {
            float4 o;
            o.x = fmaxf(merge2(acc[i][0]) + bv.x, 0.f);
            o.y = fmaxf(merge2(acc[i][1]) + bv.y, 0.f);
            o.z = fmaxf(merge2(acc[i][2]) + bv.z, 0.f);
            o.w = fmaxf(merge2(acc[i][3]) + bv.w, 0.f);
            *(float4*)(sH + (warp * 8 + i) * HSTR + lane * 4) = o;
        }
    }
    __syncwarp();

    // ---- GEMM2: 64 x 128 @ 128 x 128, K packed in pairs ----
    ull acc2[8][4];
    #pragma unroll
    for (int i = 0; i < 8; i++)
        #pragma unroll
        for (int c = 0; c < 4; c++) acc2[i][c] = 0ull;

    {
        const float* hbase = sH + (warp * 8) * HSTR;
        const float4* Wv = (const float4*)W2 + lane;
        #pragma unroll 2
        for (int p = 0; p < HD / 2; p++) {
            int k = 2 * p;
            float4 w0 = Wv[(size_t)k * 32];
            float4 w1 = Wv[(size_t)(k + 1) * 32];
            ull wx = pack2(w0.x, w1.x);
            ull wy = pack2(w0.y, w1.y);
            ull wz = pack2(w0.z, w1.z);
            ull ww = pack2(w0.w, w1.w);
            #pragma unroll
            for (int i = 0; i < 8; i++) {
                ull a = *(const ull*)(hbase + i * HSTR + k);
                acc2[i][0] = fma2(a, wx, acc2[i][0]);
                acc2[i][1] = fma2(a, wy, acc2[i][1]);
                acc2[i][2] = fma2(a, wz, acc2[i][2]);
                acc2[i][3] = fma2(a, ww, acc2[i][3]);
            }
        }
    }

    // bias + relu -> vector reduction into g_sums
    {
        float4 b2v = ((const float4*)b2)[lane];
        #pragma unroll
        for (int i = 0; i < 8; i++) {
            int node = sNode[warp * 8 + i];
            float vx = fmaxf(merge2(acc2[i][0]) + b2v.x, 0.f);
            float vy = fmaxf(merge2(acc2[i][1]) + b2v.y, 0.f);
            float vz = fmaxf(merge2(acc2[i][2]) + b2v.z, 0.f);
            float vw = fmaxf(merge2(acc2[i][3]) + b2v.w, 0.f);
            float* dst = g_sums + node * HD + lane * 4;
            asm volatile("red.global.add.v4.f32 [%0], {%1, %2, %3, %4};"
                         :: "l"(dst), "f"(vx), "f"(vy), "f"(vz), "f"(vw) : "memory");
        }
    }
    if (tid < 64) atomicAdd(g_cnt + sNode[tid], 1.0f);
}

// ---------------- Node kernel (legacy scalar path, ~3% of runtime) ----------------
template<int KTOT, int KVALID>
__device__ __forceinline__ void gemm_tile(const float* __restrict__ S, int sstride,
                                          const float* __restrict__ Wg,
                                          float* sW, int warp, int lane,
                                          float acc[8][4])
{
    const float* fbase = S + (warp * 8) * sstride;
    for (int kt = 0; kt < KTOT; kt += 8) {
        __syncthreads();
        for (int idx = (int)threadIdx.x; idx < 8 * HD; idx += 256) {
            int k = kt + (idx >> 7);
            sW[idx] = (k < KVALID) ? Wg[k * HD + (idx & 127)] : 0.0f;
        }
        __syncthreads();
        #pragma unroll
        for (int kk = 0; kk < 8; kk++) {
            float4 w = *(const float4*)(sW + kk * HD + lane * 4);
            #pragma unroll
            for (int i = 0; i < 8; i++) {
                float a = fbase[i * sstride + kt + kk];
                acc[i][0] += a * w.x;
                acc[i][1] += a * w.y;
                acc[i][2] += a * w.z;
                acc[i][3] += a * w.w;
            }
        }
    }
}

__global__ __launch_bounds__(256, 1)
void node_kernel(const float* __restrict__ xfeat, const float* __restrict__ T_R,
                 const float* __restrict__ T_t,  const float* __restrict__ u,
                 const int* __restrict__ batch,
                 const float* __restrict__ W3, const float* __restrict__ b3,
                 const float* __restrict__ W4, const float* __restrict__ b4,
                 float* __restrict__ out)
{
    extern __shared__ float sm[];
    float* sG    = sm;                    // 64 x GSTR
    float* sW    = sG + 64 * GSTR;        // 8 x 128 staging
    float* sH    = sW + 8 * HD;           // 64 x NHSTR
    float* sW4   = sH + 64 * NHSTR;       // 128 x 70
    float* sPose = sW4 + HD * 70;         // 64 x 6

    int tid = threadIdx.x;
    int n0 = blockIdx.x * 64;

    for (int idx = tid; idx < 64 * HD; idx += 256) {
        int r = idx >> 7, c = idx & 127;
        int n = n0 + r;
        float v = 0.f;
        if (n < NN) v = g_sums[n * HD + c] / fmaxf(g_cnt[n], 1.0f);
        sG[r * GSTR + c] = v;
    }
    for (int idx = tid; idx < 64 * ND; idx += 256) {
        int r = idx >> 6, c = idx & 63;
        int n = n0 + r;
        sG[r * GSTR + HD + c] = (n < NN) ? xfeat[n * ND + c] : 0.f;
    }
    for (int idx = tid; idx < 64 * GD; idx += 256) {
        int r = idx >> 5, c = idx & 31;
        int n = n0 + r;
        sG[r * GSTR + HD + ND + c] = (n < NN) ? u[batch[n] * GD + c] : 0.f;
    }

    int warp = tid >> 5, lane = tid & 31;
    float acc[8][4];
    #pragma unroll
    for (int i = 0; i < 8; i++) { acc[i][0]=0.f; acc[i][1]=0.f; acc[i][2]=0.f; acc[i][3]=0.f; }
    gemm_tile<K3, K3>(sG, GSTR, W3, sW, warp, lane, acc);

    float4 bv = *(const float4*)(b3 + lane * 4);
    #pragma unroll
    for (int i = 0; i < 8; i++) {
        float4 o;
        o.x = fmaxf(acc[i][0] + bv.x, 0.f);
        o.y = fmaxf(acc[i][1] + bv.y, 0.f);
        o.z = fmaxf(acc[i][2] + bv.z, 0.f);
        o.w = fmaxf(acc[i][3] + bv.w, 0.f);
        *(float4*)(sH + (warp * 8 + i) * NHSTR + lane * 4) = o;
    }
    __syncthreads();
    for (int idx = tid; idx < HD * 70; idx += 256) sW4[idx] = W4[idx];
    __syncthreads();

    float a4[8][3];
    #pragma unroll
    for (int i = 0; i < 8; i++) { a4[i][0]=0.f; a4[i][1]=0.f; a4[i][2]=0.f; }
    const float* hb = sH + warp * 8 * NHSTR;
    for (int k = 0; k < HD; k++) {
        float w0 = sW4[k * 70 + lane];
        float w1 = sW4[k * 70 + 32 + lane];
        float w2 = (lane < DOF) ? sW4[k * 70 + 64 + lane] : 0.f;
        #pragma unroll
        for (int i = 0; i < 8; i++) {
            float a = hb[i * NHSTR + k];
            a4[i][0] += a * w0;
            a4[i][1] += a * w1;
            a4[i][2] += a * w2;
        }
    }
    float bb0 = b4[lane], bb1 = b4[32 + lane];
    float bb2 = (lane < DOF) ? b4[64 + lane] : 0.f;
    #pragma unroll
    for (int i = 0; i < 8; i++) {
        int r = warp * 8 + i;
        int n = n0 + r;
        if (n < NN) {
            out[(size_t)n * 77 + lane]      = xfeat[n * ND + lane]      + a4[i][0] + bb0;
            out[(size_t)n * 77 + 32 + lane] = xfeat[n * ND + 32 + lane] + a4[i][1] + bb1;
        }
        if (lane < DOF) sPose[r * DOF + lane] = a4[i][2] + bb2;
    }
    __syncthreads();

    if (tid < 64) {
        int n = n0 + tid;
        if (n < NN) {
            float r0 = sPose[tid*6+0], r1 = sPose[tid*6+1], r2 = sPose[tid*6+2];
            float px = sPose[tid*6+3], py = sPose[tid*6+4], pz = sPose[tid*6+5];
            float nr = sqrtf(px*px + py*py + pz*pz);
            float sc = PI_F * tanhf(nr / PI_F) / (nr + 1e-8f);
            px *= sc; py *= sc; pz *= sc;
            float pp = px*px + py*py + pz*pz;
            float th = sqrtf(pp + 1e-12f);
            float a, b, c;
            if (th < 1e-4f) {
                a = 1.f - pp/6.f; b = 0.5f - pp/24.f; c = 1.f/6.f - pp/120.f;
            } else {
                float s = sinf(th), co = cosf(th);
                a = s / th; b = (1.f - co) / pp; c = (th - s) / (pp * th);
            }
            float Km[9] = {0.f,-pz,py,  pz,0.f,-px,  -py,px,0.f};
            float KK[9] = {px*px-pp, px*py,    px*pz,
                           py*px,    py*py-pp, py*pz,
                           pz*px,    pz*py,    pz*pz-pp};
            float Rd[9], V[9];
            #pragma unroll
            for (int q = 0; q < 9; q++) { Rd[q] = a*Km[q] + b*KK[q]; V[q] = b*Km[q] + c*KK[q]; }
            Rd[0] += 1.f; Rd[4] += 1.f; Rd[8] += 1.f;
            V[0]  += 1.f; V[4]  += 1.f; V[8]  += 1.f;
            float td0 = V[0]*r0 + V[1]*r1 + V[2]*r2;
            float td1 = V[3]*r0 + V[4]*r1 + V[5]*r2;
            float td2 = V[6]*r0 + V[7]*r1 + V[8]*r2;
            float TR[9], Tt[3];
            #pragma unroll
            for (int q = 0; q < 9; q++) TR[q] = T_R[n*9+q];
            #pragma unroll
            for (int q = 0; q < 3; q++) Tt[q] = T_t[n*3+q];
            float* o = out + (size_t)n * 77;
            #pragma unroll
            for (int rr = 0; rr < 3; rr++) {
                #pragma unroll
                for (int cc = 0; cc < 3; cc++) {
                    o[64 + rr*3 + cc] = Rd[rr*3+0]*TR[0+cc] + Rd[rr*3+1]*TR[3+cc] + Rd[rr*3+2]*TR[6+cc];
                }
                o[73 + rr] = Rd[rr*3+0]*Tt[0] + Rd[rr*3+1]*Tt[1] + Rd[rr*3+2]*Tt[2]
                           + (rr == 0 ? td0 : (rr == 1 ? td1 : td2));
            }
            o[76] = sqrtf(pp);
        }
    }
}

extern "C" void kernel_launch(void* const* d_in, const int* in_sizes, int n_in,
                              void* d_out, int out_size) {
    const float* xfeat     = (const float*)d_in[0];
    const float* T_R       = (const float*)d_in[1];
    const float* T_t       = (const float*)d_in[2];
    const float* edge_feat = (const float*)d_in[3];
    const float* TijR      = (const float*)d_in[4];
    const float* Tijt      = (const float*)d_in[5];
    const float* u         = (const float*)d_in[6];
    const int*   ei        = (const int*)d_in[7];
    const int*   batch     = (const int*)d_in[8];
    const float* W1 = (const float*)d_in[9];
    const float* b1 = (const float*)d_in[10];
    const float* W2 = (const float*)d_in[11];
    const float* b2 = (const float*)d_in[12];
    const float* W3 = (const float*)d_in[13];
    const float* b3 = (const float*)d_in[14];
    const float* W4 = (const float*)d_in[15];
    const float* b4 = (const float*)d_in[16];
    float* out = (float*)d_out;

    // pad edge smem to force 1 block/SM -> L1D carveout (~112KB) holds W1/W2
    const int ESMEM = 118784;
    const int NSMEM = (64 * GSTR + 8 * HD + 64 * NHSTR + HD * 70 + 64 * DOF) * 4;
    cudaFuncSetAttribute(edge_kernel, cudaFuncAttributeMaxDynamicSharedMemorySize, ESMEM);
    cudaFuncSetAttribute(node_kernel, cudaFuncAttributeMaxDynamicSharedMemorySize, NSMEM);

    zero_kernel<<<(NN * HD / 4 + 255) / 256, 256>>>();
    edge_kernel<<<EE / 32, 256, ESMEM>>>(xfeat, T_R, T_t, edge_feat, TijR, Tijt,
                                         ei, W1, b1, W2, b2);
    node_kernel<<<(NN + 63) / 64, 256, NSMEM>>>(xfeat, T_R, T_t, u, batch,
                                                W3, b3, W4, b4, out);
}

// round 3
// speedup vs baseline: 1.2368x; 1.2368x over previous
#include <cuda_runtime.h>
#include <math.h>

#define NN 20000
#define EE 200000
#define ND 64
#define ED 32
#define GD 32
#define HD 128
#define DOF 6
#define PI_F 3.14159265358979f

#define K1   172   // edge MLP input width (even -> 86 k-pairs)
#define FSTR 172   // smem stride of feature tile
#define HSTR 128   // smem stride of hidden tile
#define K3   224   // node MLP input width
#define GSTR 224
#define NHSTR 132  // node kernel hidden stride

#define EPB 64     // edges per block
#define RPB 128    // rows per block (2*EPB)
#define TPB 512    // threads per block

typedef unsigned long long ull;

// scratch accumulators (no cudaMalloc allowed)
__device__ float g_sums[NN * HD];
__device__ float g_cnt[NN];

__global__ void zero_kernel() {
    int idx = blockIdx.x * blockDim.x + threadIdx.x;
    if (idx < NN * HD / 4) ((float4*)g_sums)[idx] = make_float4(0.f, 0.f, 0.f, 0.f);
    if (idx < NN)          g_cnt[idx] = 0.0f;
}

__device__ __forceinline__ ull fma2(ull a, ull b, ull c) {
    ull d;
    asm("fma.rn.f32x2 %0, %1, %2, %3;" : "=l"(d) : "l"(a), "l"(b), "l"(c));
    return d;
}
__device__ __forceinline__ ull pack2(float lo, float hi) {
    ull d;
    asm("mov.b64 %0, {%1, %2};" : "=l"(d) : "f"(lo), "f"(hi));
    return d;
}
__device__ __forceinline__ float merge2(ull v) {
    float lo, hi;
    asm("mov.b64 {%0, %1}, %2;" : "=f"(lo), "=f"(hi) : "l"(v));
    return lo + hi;
}

// ---------------- Edge kernel: 64 edges (128 rows), 512 threads, 16 warps ----------------
// warp owns rows warp*8..warp*8+7; lane owns cols lane*4..lane*4+3.
// K packed in pairs via fma.rn.f32x2; W read from global with software prefetch.
__global__ __launch_bounds__(TPB, 1)
void edge_kernel(const float* __restrict__ xfeat, const float* __restrict__ T_R,
                 const float* __restrict__ T_t,  const float* __restrict__ edge_feat,
                 const float* __restrict__ TijR, const float* __restrict__ Tijt,
                 const int* __restrict__ ei,
                 const float* __restrict__ W1, const float* __restrict__ b1,
                 const float* __restrict__ W2, const float* __restrict__ b2)
{
    extern __shared__ float sm[];
    float* sF = sm;                  // RPB x FSTR  (88064 B)
    float* sH = sF + RPB * FSTR;     // RPB x HSTR  (65536 B)
    __shared__ int sNode[RPB];

    int tid = threadIdx.x;
    int e0 = blockIdx.x * EPB;

    // ---- feature copy: xfeat_i, xfeat_j, edge_feat (8 threads per edge) ----
    {
        int sub = tid & 7;
        int el  = tid >> 3;              // local edge 0..63
        int e   = e0 + el;
        int vi = ei[e], vj = ei[EE + e];
        const float4* xi4 = (const float4*)(xfeat + vi * ND);
        const float4* xj4 = (const float4*)(xfeat + vj * ND);
        const float4* ef4 = (const float4*)(edge_feat + e * ED);
        float* rowA = sF + el * FSTR;           // f_ij  (rows 0..63)
        float* rowB = sF + (EPB + el) * FSTR;   // f_ji  (rows 64..127)
        #pragma unroll
        for (int q = sub; q < 16; q += 8) {
            float4 v = xi4[q];
            *(float4*)(rowA + q * 4)       = v;
            *(float4*)(rowB + 64 + q * 4)  = v;
            float4 w = xj4[q];
            *(float4*)(rowA + 64 + q * 4)  = w;
            *(float4*)(rowB + q * 4)       = w;
        }
        float4 v = ef4[sub];
        *(float4*)(rowA + 128 + sub * 4) = v;
        *(float4*)(rowB + 128 + sub * 4) = v;
    }

    // ---- relative pose features (1 thread per edge) ----
    if (tid < EPB) {
        int e = e0 + tid;
        int vi = ei[e], vj = ei[EE + e];
        sNode[tid]       = vj;   // f_ij aggregates into j
        sNode[EPB + tid] = vi;   // f_ji aggregates into i
        float Ri[9], Rj[9], Tr[9], ti[3], tj[3], tt[3];
        #pragma unroll
        for (int k = 0; k < 9; k++) { Ri[k] = T_R[vi*9+k]; Rj[k] = T_R[vj*9+k]; Tr[k] = TijR[e*9+k]; }
        #pragma unroll
        for (int k = 0; k < 3; k++) { ti[k] = T_t[vi*3+k]; tj[k] = T_t[vj*3+k]; tt[k] = Tijt[e*3+k]; }
        float A[9], ta[3];
        #pragma unroll
        for (int r = 0; r < 3; r++)
            #pragma unroll
            for (int c = 0; c < 3; c++)
                A[r*3+c] = Rj[r*3+0]*Ri[c*3+0] + Rj[r*3+1]*Ri[c*3+1] + Rj[r*3+2]*Ri[c*3+2];
        #pragma unroll
        for (int r = 0; r < 3; r++)
            ta[r] = tj[r] - (A[r*3+0]*ti[0] + A[r*3+1]*ti[1] + A[r*3+2]*ti[2]);
        float Re[9], te[3];
        #pragma unroll
        for (int r = 0; r < 3; r++)
            #pragma unroll
            for (int c = 0; c < 3; c++)
                Re[r*3+c] = A[r*3+0]*Tr[c*3+0] + A[r*3+1]*Tr[c*3+1] + A[r*3+2]*Tr[c*3+2];
        #pragma unroll
        for (int r = 0; r < 3; r++)
            te[r] = ta[r] - (Re[r*3+0]*tt[0] + Re[r*3+1]*tt[1] + Re[r*3+2]*tt[2]);
        float* fA = sF + tid * FSTR + 160;
        fA[0]=Re[0]; fA[1]=Re[1]; fA[2]=Re[2];  fA[3]=te[0];
        fA[4]=Re[3]; fA[5]=Re[4]; fA[6]=Re[5];  fA[7]=te[1];
        fA[8]=Re[6]; fA[9]=Re[7]; fA[10]=Re[8]; fA[11]=te[2];
        float tb[3], Rf[9], tf[3];
        #pragma unroll
        for (int r = 0; r < 3; r++)
            tb[r] = ti[r] - (A[0+r]*tj[0] + A[3+r]*tj[1] + A[6+r]*tj[2]);
        #pragma unroll
        for (int r = 0; r < 3; r++)
            #pragma unroll
            for (int c = 0; c < 3; c++)
                Rf[r*3+c] = A[0+r]*Tr[0+c] + A[3+r]*Tr[3+c] + A[6+r]*Tr[6+c];
        #pragma unroll
        for (int r = 0; r < 3; r++)
            tf[r] = tb[r] + (A[0+r]*tt[0] + A[3+r]*tt[1] + A[6+r]*tt[2]);
        float* fB = sF + (EPB + tid) * FSTR + 160;
        fB[0]=Rf[0]; fB[1]=Rf[1]; fB[2]=Rf[2];  fB[3]=tf[0];
        fB[4]=Rf[3]; fB[5]=Rf[4]; fB[6]=Rf[5];  fB[7]=tf[1];
        fB[8]=Rf[6]; fB[9]=Rf[7]; fB[10]=Rf[8]; fB[11]=tf[2];
    }
    __syncthreads();

    int warp = tid >> 5, lane = tid & 31;
    const float* fbase = sF + (warp * 8) * FSTR;

    // ---- GEMM1: 128 x 172 @ 172 x 128, K packed in pairs, prefetched W ----
    ull acc[8][4];
    #pragma unroll
    for (int i = 0; i < 8; i++)
        #pragma unroll
        for (int c = 0; c < 4; c++) acc[i][c] = 0ull;

    {
        const float4* Wv = (const float4*)W1 + lane;
        float4 w0 = Wv[0];
        float4 w1 = Wv[32];
        #pragma unroll 2
        for (int p = 0; p < K1 / 2; p++) {
            float4 n0, n1;
            if (p < K1 / 2 - 1) {
                n0 = Wv[(size_t)(2 * p + 2) * 32];
                n1 = Wv[(size_t)(2 * p + 3) * 32];
            }
            ull wx = pack2(w0.x, w1.x);
            ull wy = pack2(w0.y, w1.y);
            ull wz = pack2(w0.z, w1.z);
            ull ww = pack2(w0.w, w1.w);
            int k = 2 * p;
            #pragma unroll
            for (int i = 0; i < 8; i++) {
                ull a = *(const ull*)(fbase + i * FSTR + k);
                acc[i][0] = fma2(a, wx, acc[i][0]);
                acc[i][1] = fma2(a, wy, acc[i][1]);
                acc[i][2] = fma2(a, wz, acc[i][2]);
                acc[i][3] = fma2(a, ww, acc[i][3]);
            }
            w0 = n0; w1 = n1;
        }
    }

    // bias + relu -> sH (warp-private rows; no block barrier needed)
    {
        float4 bv = ((const float4*)b1)[lane];
        #pragma unroll
        for (int i = 0; i < 8; i++) {
            float4 o;
            o.x = fmaxf(merge2(acc[i][0]) + bv.x, 0.f);
            o.y = fmaxf(merge2(acc[i][1]) + bv.y, 0.f);
            o.z = fmaxf(merge2(acc[i][2]) + bv.z, 0.f);
            o.w = fmaxf(merge2(acc[i][3]) + bv.w, 0.f);
            *(float4*)(sH + (warp * 8 + i) * HSTR + lane * 4) = o;
        }
    }
    __syncwarp();

    // ---- GEMM2: 128 x 128 @ 128 x 128, K packed in pairs, prefetched W ----
    ull acc2[8][4];
    #pragma unroll
    for (int i = 0; i < 8; i++)
        #pragma unroll
        for (int c = 0; c < 4; c++) acc2[i][c] = 0ull;

    {
        const float* hbase = sH + (warp * 8) * HSTR;
        const float4* Wv = (const float4*)W2 + lane;
        float4 w0 = Wv[0];
        float4 w1 = Wv[32];
        #pragma unroll 2
        for (int p = 0; p < HD / 2; p++) {
            float4 n0, n1;
            if (p < HD / 2 - 1) {
                n0 = Wv[(size_t)(2 * p + 2) * 32];
                n1 = Wv[(size_t)(2 * p + 3) * 32];
            }
            ull wx = pack2(w0.x, w1.x);
            ull wy = pack2(w0.y, w1.y);
            ull wz = pack2(w0.z, w1.z);
            ull ww = pack2(w0.w, w1.w);
            int k = 2 * p;
            #pragma unroll
            for (int i = 0; i < 8; i++) {
                ull a = *(const ull*)(hbase + i * HSTR + k);
                acc2[i][0] = fma2(a, wx, acc2[i][0]);
                acc2[i][1] = fma2(a, wy, acc2[i][1]);
                acc2[i][2] = fma2(a, wz, acc2[i][2]);
                acc2[i][3] = fma2(a, ww, acc2[i][3]);
            }
            w0 = n0; w1 = n1;
        }
    }

    // bias + relu -> vector reduction into g_sums
    {
        float4 b2v = ((const float4*)b2)[lane];
        #pragma unroll
        for (int i = 0; i < 8; i++) {
            int node = sNode[warp * 8 + i];
            float vx = fmaxf(merge2(acc2[i][0]) + b2v.x, 0.f);
            float vy = fmaxf(merge2(acc2[i][1]) + b2v.y, 0.f);
            float vz = fmaxf(merge2(acc2[i][2]) + b2v.z, 0.f);
            float vw = fmaxf(merge2(acc2[i][3]) + b2v.w, 0.f);
            float* dst = g_sums + node * HD + lane * 4;
            asm volatile("red.global.add.v4.f32 [%0], {%1, %2, %3, %4};"
                         :: "l"(dst), "f"(vx), "f"(vy), "f"(vz), "f"(vw) : "memory");
        }
    }
    if (tid < RPB) atomicAdd(g_cnt + sNode[tid], 1.0f);
}

// ---------------- Node kernel (scalar path, small share of runtime) ----------------
template<int KTOT, int KVALID>
__device__ __forceinline__ void gemm_tile(const float* __restrict__ S, int sstride,
                                          const float* __restrict__ Wg,
                                          float* sW, int warp, int lane,
                                          float acc[8][4])
{
    const float* fbase = S + (warp * 8) * sstride;
    for (int kt = 0; kt < KTOT; kt += 8) {
        __syncthreads();
        for (int idx = (int)threadIdx.x; idx < 8 * HD; idx += 256) {
            int k = kt + (idx >> 7);
            sW[idx] = (k < KVALID) ? Wg[k * HD + (idx & 127)] : 0.0f;
        }
        __syncthreads();
        #pragma unroll
        for (int kk = 0; kk < 8; kk++) {
            float4 w = *(const float4*)(sW + kk * HD + lane * 4);
            #pragma unroll
            for (int i = 0; i < 8; i++) {
                float a = fbase[i * sstride + kt + kk];
                acc[i][0] += a * w.x;
                acc[i][1] += a * w.y;
                acc[i][2] += a * w.z;
                acc[i][3] += a * w.w;
            }
        }
    }
}

__global__ __launch_bounds__(256, 1)
void node_kernel(const float* __restrict__ xfeat, const float* __restrict__ T_R,
                 const float* __restrict__ T_t,  const float* __restrict__ u,
                 const int* __restrict__ batch,
                 const float* __restrict__ W3, const float* __restrict__ b3,
                 const float* __restrict__ W4, const float* __restrict__ b4,
                 float* __restrict__ out)
{
    extern __shared__ float sm[];
    float* sG    = sm;                    // 64 x GSTR
    float* sW    = sG + 64 * GSTR;        // 8 x 128 staging
    float* sH    = sW + 8 * HD;           // 64 x NHSTR
    float* sW4   = sH + 64 * NHSTR;       // 128 x 70
    float* sPose = sW4 + HD * 70;         // 64 x 6

    int tid = threadIdx.x;
    int n0 = blockIdx.x * 64;

    for (int idx = tid; idx < 64 * HD; idx += 256) {
        int r = idx >> 7, c = idx & 127;
        int n = n0 + r;
        float v = 0.f;
        if (n < NN) v = g_sums[n * HD + c] / fmaxf(g_cnt[n], 1.0f);
        sG[r * GSTR + c] = v;
    }
    for (int idx = tid; idx < 64 * ND; idx += 256) {
        int r = idx >> 6, c = idx & 63;
        int n = n0 + r;
        sG[r * GSTR + HD + c] = (n < NN) ? xfeat[n * ND + c] : 0.f;
    }
    for (int idx = tid; idx < 64 * GD; idx += 256) {
        int r = idx >> 5, c = idx & 31;
        int n = n0 + r;
        sG[r * GSTR + HD + ND + c] = (n < NN) ? u[batch[n] * GD + c] : 0.f;
    }

    int warp = tid >> 5, lane = tid & 31;
    float acc[8][4];
    #pragma unroll
    for (int i = 0; i < 8; i++) { acc[i][0]=0.f; acc[i][1]=0.f; acc[i][2]=0.f; acc[i][3]=0.f; }
    gemm_tile<K3, K3>(sG, GSTR, W3, sW, warp, lane, acc);

    float4 bv = *(const float4*)(b3 + lane * 4);
    #pragma unroll
    for (int i = 0; i < 8; i++) {
        float4 o;
        o.x = fmaxf(acc[i][0] + bv.x, 0.f);
        o.y = fmaxf(acc[i][1] + bv.y, 0.f);
        o.z = fmaxf(acc[i][2] + bv.z, 0.f);
        o.w = fmaxf(acc[i][3] + bv.w, 0.f);
        *(float4*)(sH + (warp * 8 + i) * NHSTR + lane * 4) = o;
    }
    __syncthreads();
    for (int idx = tid; idx < HD * 70; idx += 256) sW4[idx] = W4[idx];
    __syncthreads();

    float a4[8][3];
    #pragma unroll
    for (int i = 0; i < 8; i++) { a4[i][0]=0.f; a4[i][1]=0.f; a4[i][2]=0.f; }
    const float* hb = sH + warp * 8 * NHSTR;
    for (int k = 0; k < HD; k++) {
        float w0 = sW4[k * 70 + lane];
        float w1 = sW4[k * 70 + 32 + lane];
        float w2 = (lane < DOF) ? sW4[k * 70 + 64 + lane] : 0.f;
        #pragma unroll
        for (int i = 0; i < 8; i++) {
            float a = hb[i * NHSTR + k];
            a4[i][0] += a * w0;
            a4[i][1] += a * w1;
            a4[i][2] += a * w2;
        }
    }
    float bb0 = b4[lane], bb1 = b4[32 + lane];
    float bb2 = (lane < DOF) ? b4[64 + lane] : 0.f;
    #pragma unroll
    for (int i = 0; i < 8; i++) {
        int r = warp * 8 + i;
        int n = n0 + r;
        if (n < NN) {
            out[(size_t)n * 77 + lane]      = xfeat[n * ND + lane]      + a4[i][0] + bb0;
            out[(size_t)n * 77 + 32 + lane] = xfeat[n * ND + 32 + lane] + a4[i][1] + bb1;
        }
        if (lane < DOF) sPose[r * DOF + lane] = a4[i][2] + bb2;
    }
    __syncthreads();

    if (tid < 64) {
        int n = n0 + tid;
        if (n < NN) {
            float r0 = sPose[tid*6+0], r1 = sPose[tid*6+1], r2 = sPose[tid*6+2];
            float px = sPose[tid*6+3], py = sPose[tid*6+4], pz = sPose[tid*6+5];
            float nr = sqrtf(px*px + py*py + pz*pz);
            float sc = PI_F * tanhf(nr / PI_F) / (nr + 1e-8f);
            px *= sc; py *= sc; pz *= sc;
            float pp = px*px + py*py + pz*pz;
            float th = sqrtf(pp + 1e-12f);
            float a, b, c;
            if (th < 1e-4f) {
                a = 1.f - pp/6.f; b = 0.5f - pp/24.f; c = 1.f/6.f - pp/120.f;
            } else {
                float s = sinf(th), co = cosf(th);
                a = s / th; b = (1.f - co) / pp; c = (th - s) / (pp * th);
            }
            float Km[9] = {0.f,-pz,py,  pz,0.f,-px,  -py,px,0.f};
            float KK[9] = {px*px-pp, px*py,    px*pz,
                           py*px,    py*py-pp, py*pz,
                           pz*px,    pz*py,    pz*pz-pp};
            float Rd[9], V[9];
            #pragma unroll
            for (int q = 0; q < 9; q++) { Rd[q] = a*Km[q] + b*KK[q]; V[q] = b*Km[q] + c*KK[q]; }
            Rd[0] += 1.f; Rd[4] += 1.f; Rd[8] += 1.f;
            V[0]  += 1.f; V[4]  += 1.f; V[8]  += 1.f;
            float td0 = V[0]*r0 + V[1]*r1 + V[2]*r2;
            float td1 = V[3]*r0 + V[4]*r1 + V[5]*r2;
            float td2 = V[6]*r0 + V[7]*r1 + V[8]*r2;
            float TR[9], Tt[3];
            #pragma unroll
            for (int q = 0; q < 9; q++) TR[q] = T_R[n*9+q];
            #pragma unroll
            for (int q = 0; q < 3; q++) Tt[q] = T_t[n*3+q];
            float* o = out + (size_t)n * 77;
            #pragma unroll
            for (int rr = 0; rr < 3; rr++) {
                #pragma unroll
                for (int cc = 0; cc < 3; cc++) {
                    o[64 + rr*3 + cc] = Rd[rr*3+0]*TR[0+cc] + Rd[rr*3+1]*TR[3+cc] + Rd[rr*3+2]*TR[6+cc];
                }
                o[73 + rr] = Rd[rr*3+0]*Tt[0] + Rd[rr*3+1]*Tt[1] + Rd[rr*3+2]*Tt[2]
                           + (rr == 0 ? td0 : (rr == 1 ? td1 : td2));
            }
            o[76] = sqrtf(pp);
        }
    }
}

extern "C" void kernel_launch(void* const* d_in, const int* in_sizes, int n_in,
                              void* d_out, int out_size) {
    const float* xfeat     = (const float*)d_in[0];
    const float* T_R       = (const float*)d_in[1];
    const float* T_t       = (const float*)d_in[2];
    const float* edge_feat = (const float*)d_in[3];
    const float* TijR      = (const float*)d_in[4];
    const float* Tijt      = (const float*)d_in[5];
    const float* u         = (const float*)d_in[6];
    const int*   ei        = (const int*)d_in[7];
    const int*   batch     = (const int*)d_in[8];
    const float* W1 = (const float*)d_in[9];
    const float* b1 = (const float*)d_in[10];
    const float* W2 = (const float*)d_in[11];
    const float* b2 = (const float*)d_in[12];
    const float* W3 = (const float*)d_in[13];
    const float* b3 = (const float*)d_in[14];
    const float* W4 = (const float*)d_in[15];
    const float* b4 = (const float*)d_in[16];
    float* out = (float*)d_out;

    const int ESMEM = (RPB * FSTR + RPB * HSTR) * 4;  // 153600 B
    const int NSMEM = (64 * GSTR + 8 * HD + 64 * NHSTR + HD * 70 + 64 * DOF) * 4;
    cudaFuncSetAttribute(edge_kernel, cudaFuncAttributeMaxDynamicSharedMemorySize, ESMEM);
    cudaFuncSetAttribute(node_kernel, cudaFuncAttributeMaxDynamicSharedMemorySize, NSMEM);

    zero_kernel<<<(NN * HD / 4 + 255) / 256, 256>>>();
    edge_kernel<<<EE / EPB, TPB, ESMEM>>>(xfeat, T_R, T_t, edge_feat, TijR, Tijt,
                                          ei, W1, b1, W2, b2);
    node_kernel<<<(NN + 63) / 64, 256, NSMEM>>>(xfeat, T_R, T_t, u, batch,
                                                W3, b3, W4, b4, out);
}

// round 6
// speedup vs baseline: 2.1363x; 1.7272x over previous
#include <cuda_runtime.h>
#include <cuda_bf16.h>
#include <math.h>

#define NN 20000
#define EE 200000
#define ND 64
#define ED 32
#define GD 32
#define HD 128
#define DOF 6
#define PI_F 3.14159265358979f

#define K3   224
#define GSTR 224
#define NHSTR 132

#define EPB 64
#define RPB 128
#define TPB 512

// pitched bf16 smem tiles: pitch 200 els = 400 B (== 16 mod 128 -> ldmatrix conflict-free)
#define SP   200
#define SPB  400
#define IMG  (128 * SPB)      // 51200 B per image
#define OFF_AH 0
#define OFF_AL IMG
#define OFF_BH (2 * IMG)
#define OFF_BL (3 * IMG)
#define ESMEM  (4 * IMG)      // 204800 B

static __device__ __align__(16) __nv_bfloat16 gW1h[128 * SP];
static __device__ __align__(16) __nv_bfloat16 gW1l[128 * SP];
static __device__ __align__(16) __nv_bfloat16 gW2h[128 * SP];
static __device__ __align__(16) __nv_bfloat16 gW2l[128 * SP];

__device__ float g_sums[NN * HD];
__device__ float g_cnt[NN];

__device__ __forceinline__ unsigned smem_u32(const void* p) {
    unsigned a;
    asm("{ .reg .u64 t; cvta.to.shared.u64 t, %1; cvt.u32.u64 %0, t; }" : "=r"(a) : "l"(p));
    return a;
}
__device__ __forceinline__ void split2(float a, float b, unsigned& hi, unsigned& lo) {
    __nv_bfloat16 ha = __float2bfloat16(a), hb = __float2bfloat16(b);
    __nv_bfloat162 th; th.x = ha; th.y = hb;
    hi = *(unsigned*)&th;
    __nv_bfloat162 tl;
    tl.x = __float2bfloat16(a - __bfloat162float(ha));
    tl.y = __float2bfloat16(b - __bfloat162float(hb));
    lo = *(unsigned*)&tl;
}
__device__ __forceinline__ void split4v(float4 v, uint2& hi, uint2& lo) {
    unsigned h0, l0, h1, l1;
    split2(v.x, v.y, h0, l0);
    split2(v.z, v.w, h1, l1);
    hi = make_uint2(h0, h1);
    lo = make_uint2(l0, l1);
}
__device__ __forceinline__ unsigned eoff(int r, int k) { return (unsigned)(r * SPB + k * 2); }

__device__ __forceinline__ void ldm4(unsigned addr, unsigned* r) {
    asm volatile("ldmatrix.sync.aligned.m8n8.x4.shared.b16 {%0,%1,%2,%3}, [%4];"
        : "=r"(r[0]), "=r"(r[1]), "=r"(r[2]), "=r"(r[3]) : "r"(addr));
}
__device__ __forceinline__ void mma16816(float* d, const unsigned* a, unsigned b0, unsigned b1) {
    asm volatile("mma.sync.aligned.m16n8k16.row.col.f32.bf16.bf16.f32 "
        "{%0,%1,%2,%3}, {%4,%5,%6,%7}, {%8,%9}, {%0,%1,%2,%3};"
        : "+f"(d[0]), "+f"(d[1]), "+f"(d[2]), "+f"(d[3])
        : "r"(a[0]), "r"(a[1]), "r"(a[2]), "r"(a[3]), "r"(b0), "r"(b1));
}

// one warp: 32x32 output tile; KSTEPS k16-steps; accumulate into d[2][4][4]
template<int KSTEPS>
__device__ __forceinline__ void gemm_warp(unsigned aBase, unsigned bBase,
                                          unsigned aoff0, unsigned boff0,
                                          float d[2][4][4]) {
    #pragma unroll
    for (int s = 0; s < KSTEPS; s++) {
        unsigned kb = (unsigned)s * 32u;  // 16 els * 2 B
        unsigned a0[4], a1[4], b0[4], b1[4];
        ldm4(aBase + aoff0 + kb, a0);
        ldm4(aBase + aoff0 + 16u * SPB + kb, a1);
        ldm4(bBase + boff0 + kb, b0);
        ldm4(bBase + boff0 + 16u * SPB + kb, b1);
        mma16816(d[0][0], a0, b0[0], b0[1]);
        mma16816(d[0][1], a0, b0[2], b0[3]);
        mma16816(d[0][2], a0, b1[0], b1[1]);
        mma16816(d[0][3], a0, b1[2], b1[3]);
        mma16816(d[1][0], a1, b0[0], b0[1]);
        mma16816(d[1][1], a1, b0[2], b0[3]);
        mma16816(d[1][2], a1, b1[0], b1[1]);
        mma16816(d[1][3], a1, b1[2], b1[3]);
    }
}

__global__ void zero_kernel() {
    int idx = blockIdx.x * blockDim.x + threadIdx.x;
    if (idx < NN * HD / 4) ((float4*)g_sums)[idx] = make_float4(0.f, 0.f, 0.f, 0.f);
    if (idx < NN)          g_cnt[idx] = 0.0f;
}

// transpose + bf16-split weights into pitched [N][K] images
__global__ void prep_w(const float* __restrict__ W1, const float* __restrict__ W2) {
    int idx = blockIdx.x * blockDim.x + threadIdx.x;
    if (idx < 128 * 192) {
        int n = idx / 192, k = idx % 192;
        float w = (k < 172) ? W1[k * HD + n] : 0.f;
        __nv_bfloat16 h = __float2bfloat16(w);
        __nv_bfloat16 l = __float2bfloat16(w - __bfloat162float(h));
        gW1h[n * SP + k] = h; gW1l[n * SP + k] = l;
    } else if (idx < 128 * 192 + 128 * 128) {
        int j = idx - 128 * 192;
        int n = j / 128, k = j % 128;
        float w = W2[k * HD + n];
        __nv_bfloat16 h = __float2bfloat16(w);
        __nv_bfloat16 l = __float2bfloat16(w - __bfloat162float(h));
        gW2h[n * SP + k] = h; gW2l[n * SP + k] = l;
    }
}

// ---------------- Edge kernel: HMMA bf16 3-term split GEMMs ----------------
__global__ __launch_bounds__(TPB, 1)
void edge_kernel(const float* __restrict__ xfeat, const float* __restrict__ T_R,
                 const float* __restrict__ T_t,  const float* __restrict__ edge_feat,
                 const float* __restrict__ TijR, const float* __restrict__ Tijt,
                 const int* __restrict__ ei,
                 const float* __restrict__ b1, const float* __restrict__ b2)
{
    extern __shared__ __align__(16) char smraw[];
    char* sAh = smraw + OFF_AH;
    char* sAl = smraw + OFF_AL;
    char* sBh = smraw + OFF_BH;
    char* sBl = smraw + OFF_BL;
    unsigned sb = smem_u32(smraw);

    __shared__ int sNode[RPB];
    __shared__ float sBias1[HD], sBias2[HD];

    int tid = threadIdx.x;
    int warp = tid >> 5, lane = tid & 31;
    int e0 = blockIdx.x * EPB;

    if (tid < HD)          sBias1[tid] = b1[tid];
    else if (tid < 2 * HD) sBias2[tid - HD] = b2[tid - HD];

    // ---- W1 images -> smem B region ----
    {
        const float4* s1 = (const float4*)gW1h;
        const float4* s2 = (const float4*)gW1l;
        float4* d1 = (float4*)sBh;
        float4* d2 = (float4*)sBl;
        for (int i = tid; i < IMG / 16; i += TPB) { d1[i] = s1[i]; d2[i] = s2[i]; }
    }

    // ---- feature build: bf16 hi/lo pitched rows ----
    {
        int sub = tid & 7;
        int el  = tid >> 3;
        int e   = e0 + el;
        int vi = ei[e], vj = ei[EE + e];
        const float4* xi4 = (const float4*)(xfeat + vi * ND);
        const float4* xj4 = (const float4*)(xfeat + vj * ND);
        const float4* ef4 = (const float4*)(edge_feat + e * ED);
        int rA = el, rB = EPB + el;
        #pragma unroll
        for (int q = sub; q < 16; q += 8) {
            uint2 hi, lo;
            split4v(xi4[q], hi, lo);
            unsigned o1 = eoff(rA, 4 * q), o2 = eoff(rB, 64 + 4 * q);
            *(uint2*)(sAh + o1) = hi; *(uint2*)(sAl + o1) = lo;
            *(uint2*)(sAh + o2) = hi; *(uint2*)(sAl + o2) = lo;
            split4v(xj4[q], hi, lo);
            o1 = eoff(rA, 64 + 4 * q); o2 = eoff(rB, 4 * q);
            *(uint2*)(sAh + o1) = hi; *(uint2*)(sAl + o1) = lo;
            *(uint2*)(sAh + o2) = hi; *(uint2*)(sAl + o2) = lo;
        }
        uint2 hi, lo;
        split4v(ef4[sub], hi, lo);
        unsigned o1 = eoff(rA, 128 + 4 * sub), o2 = eoff(rB, 128 + 4 * sub);
        *(uint2*)(sAh + o1) = hi; *(uint2*)(sAl + o1) = lo;
        *(uint2*)(sAh + o2) = hi; *(uint2*)(sAl + o2) = lo;
    }

    // ---- relative pose (1 thread per edge) + K padding ----
    if (tid < EPB) {
        int e = e0 + tid;
        int vi = ei[e], vj = ei[EE + e];
        sNode[tid]       = vj;
        sNode[EPB + tid] = vi;
        float Ri[9], Rj[9], Tr[9], ti[3], tj[3], tt[3];
        #pragma unroll
        for (int k = 0; k < 9; k++) { Ri[k] = T_R[vi*9+k]; Rj[k] = T_R[vj*9+k]; Tr[k] = TijR[e*9+k]; }
        #pragma unroll
        for (int k = 0; k < 3; k++) { ti[k] = T_t[vi*3+k]; tj[k] = T_t[vj*3+k]; tt[k] = Tijt[e*3+k]; }
        float A[9], ta[3];
        #pragma unroll
        for (int r = 0; r < 3; r++)
            #pragma unroll
            for (int c = 0; c < 3; c++)
                A[r*3+c] = Rj[r*3+0]*Ri[c*3+0] + Rj[r*3+1]*Ri[c*3+1] + Rj[r*3+2]*Ri[c*3+2];
        #pragma unroll
        for (int r = 0; r < 3; r++)
            ta[r] = tj[r] - (A[r*3+0]*ti[0] + A[r*3+1]*ti[1] + A[r*3+2]*ti[2]);
        float arrA[12], arrB[12];
        {
            float Re[9], te[3];
            #pragma unroll
            for (int r = 0; r < 3; r++)
                #pragma unroll
                for (int c = 0; c < 3; c++)
                    Re[r*3+c] = A[r*3+0]*Tr[c*3+0] + A[r*3+1]*Tr[c*3+1] + A[r*3+2]*Tr[c*3+2];
            #pragma unroll
            for (int r = 0; r < 3; r++)
                te[r] = ta[r] - (Re[r*3+0]*tt[0] + Re[r*3+1]*tt[1] + Re[r*3+2]*tt[2]);
            arrA[0]=Re[0]; arrA[1]=Re[1]; arrA[2]=Re[2];  arrA[3]=te[0];
            arrA[4]=Re[3]; arrA[5]=Re[4]; arrA[6]=Re[5];  arrA[7]=te[1];
            arrA[8]=Re[6]; arrA[9]=Re[7]; arrA[10]=Re[8]; arrA[11]=te[2];
        }
        {
            float tb[3], Rf[9], tf[3];
            #pragma unroll
            for (int r = 0; r < 3; r++)
                tb[r] = ti[r] - (A[0+r]*tj[0] + A[3+r]*tj[1] + A[6+r]*tj[2]);
            #pragma unroll
            for (int r = 0; r < 3; r++)
                #pragma unroll
                for (int c = 0; c < 3; c++)
                    Rf[r*3+c] = A[0+r]*Tr[0+c] + A[3+r]*Tr[3+c] + A[6+r]*Tr[6+c];
            #pragma unroll
            for (int r = 0; r < 3; r++)
                tf[r] = tb[r] + (A[0+r]*tt[0] + A[3+r]*tt[1] + A[6+r]*tt[2]);
            arrB[0]=Rf[0]; arrB[1]=Rf[1]; arrB[2]=Rf[2];  arrB[3]=tf[0];
            arrB[4]=Rf[3]; arrB[5]=Rf[4]; arrB[6]=Rf[5];  arrB[7]=tf[1];
            arrB[8]=Rf[6]; arrB[9]=Rf[7]; arrB[10]=Rf[8]; arrB[11]=tf[2];
        }
        #pragma unroll
        for (int half = 0; half < 2; half++) {
            int r = half ? (EPB + tid) : tid;
            const float* arr = half ? arrB : arrA;
            #pragma unroll
            for (int m = 0; m < 6; m++) {
                unsigned hi, lo;
                split2(arr[2*m], arr[2*m+1], hi, lo);
                unsigned o = eoff(r, 160 + 2 * m);
                *(unsigned*)(sAh + o) = hi; *(unsigned*)(sAl + o) = lo;
            }
            #pragma unroll
            for (int k = 172; k < 192; k += 2) {
                unsigned o = eoff(r, k);
                *(unsigned*)(sAh + o) = 0u; *(unsigned*)(sAl + o) = 0u;
            }
        }
    }
    __syncthreads();

    const int m_base = (warp & 3) * 32;
    const int n_base = (warp >> 2) * 32;
    unsigned aoff0 = (unsigned)((m_base + (lane & 15)) * SPB + (lane >> 4) * 16);
    unsigned boff0 = (unsigned)((n_base + (lane & 7) + ((lane >> 4) & 1) * 8) * SPB
                                + ((lane >> 3) & 1) * 16);

    float d[2][4][4];
    #pragma unroll
    for (int i = 0; i < 2; i++)
        #pragma unroll
        for (int j = 0; j < 4; j++)
            #pragma unroll
            for (int c = 0; c < 4; c++) d[i][j][c] = 0.f;

    // ---- GEMM1: AhBh + AlBh + AhBl, K=192 ----
    gemm_warp<12>(sb + OFF_AH, sb + OFF_BH, aoff0, boff0, d);
    gemm_warp<12>(sb + OFF_AL, sb + OFF_BH, aoff0, boff0, d);
    gemm_warp<12>(sb + OFF_AH, sb + OFF_BL, aoff0, boff0, d);

    __syncthreads();   // all GEMM1 reads of sA/sB complete

    // ---- W2 images -> smem B region ----
    {
        const float4* s1 = (const float4*)gW2h;
        const float4* s2 = (const float4*)gW2l;
        float4* d1 = (float4*)sBh;
        float4* d2 = (float4*)sBl;
        for (int i = tid; i < IMG / 16; i += TPB) { d1[i] = s1[i]; d2[i] = s2[i]; }
    }

    // ---- epilogue1: bias+relu -> bf16 hi/lo hidden tile in sA ----
    {
        int r0b = m_base + (lane >> 2);
        int colb = n_base + 2 * (lane & 3);
        #pragma unroll
        for (int mi = 0; mi < 2; mi++) {
            #pragma unroll
            for (int nb = 0; nb < 4; nb++) {
                int col = colb + nb * 8;
                float bx = sBias1[col], by = sBias1[col + 1];
                int r0 = r0b + mi * 16, r1 = r0 + 8;
                unsigned hi, lo;
                split2(fmaxf(d[mi][nb][0] + bx, 0.f), fmaxf(d[mi][nb][1] + by, 0.f), hi, lo);
                unsigned o = eoff(r0, col);
                *(unsigned*)(sAh + o) = hi; *(unsigned*)(sAl + o) = lo;
                split2(fmaxf(d[mi][nb][2] + bx, 0.f), fmaxf(d[mi][nb][3] + by, 0.f), hi, lo);
                o = eoff(r1, col);
                *(unsigned*)(sAh + o) = hi; *(unsigned*)(sAl + o) = lo;
            }
        }
    }
    __syncthreads();

    // ---- GEMM2: K=128 ----
    #pragma unroll
    for (int i = 0; i < 2; i++)
        #pragma unroll
        for (int j = 0; j < 4; j++)
            #pragma unroll
            for (int c = 0; c < 4; c++) d[i][j][c] = 0.f;

    gemm_warp<8>(sb + OFF_AH, sb + OFF_BH, aoff0, boff0, d);
    gemm_warp<8>(sb + OFF_AL, sb + OFF_BH, aoff0, boff0, d);
    gemm_warp<8>(sb + OFF_AH, sb + OFF_BL, aoff0, boff0, d);

    // ---- epilogue2: bias+relu -> red.v2 scatter into g_sums ----
    {
        int r0b = m_base + (lane >> 2);
        int colb = n_base + 2 * (lane & 3);
        #pragma unroll
        for (int mi = 0; mi < 2; mi++) {
            int r0 = r0b + mi * 16, r1 = r0 + 8;
            int node0 = sNode[r0], node1 = sNode[r1];
            #pragma unroll
            for (int nb = 0; nb < 4; nb++) {
                int col = colb + nb * 8;
                float bx = sBias2[col], by = sBias2[col + 1];
                float v0 = fmaxf(d[mi][nb][0] + bx, 0.f);
                float v1 = fmaxf(d[mi][nb][1] + by, 0.f);
                float v2 = fmaxf(d[mi][nb][2] + bx, 0.f);
                float v3 = fmaxf(d[mi][nb][3] + by, 0.f);
                float* p0 = g_sums + (size_t)node0 * HD + col;
                float* p1 = g_sums + (size_t)node1 * HD + col;
                asm volatile("red.global.add.v2.f32 [%0], {%1, %2};"
                             :: "l"(p0), "f"(v0), "f"(v1) : "memory");
                asm volatile("red.global.add.v2.f32 [%0], {%1, %2};"
                             :: "l"(p1), "f"(v2), "f"(v3) : "memory");
            }
        }
        if ((warp >> 2) == 0 && (lane & 3) == 0) {
            int rr = lane >> 2;
            atomicAdd(g_cnt + sNode[m_base + rr],      1.0f);
            atomicAdd(g_cnt + sNode[m_base + rr + 8],  1.0f);
            atomicAdd(g_cnt + sNode[m_base + rr + 16], 1.0f);
            atomicAdd(g_cnt + sNode[m_base + rr + 24], 1.0f);
        }
    }
}

// ---------------- Node kernel (fp32 SIMT) ----------------
template<int KTOT, int KVALID>
__device__ __forceinline__ void gemm_tile(const float* __restrict__ S, int sstride,
                                          const float* __restrict__ Wg,
                                          float* sW, int warp, int lane,
                                          float acc[8][4])
{
    const float* fbase = S + (warp * 8) * sstride;
    for (int kt = 0; kt < KTOT; kt += 8) {
        __syncthreads();
        for (int idx = (int)threadIdx.x; idx < 8 * HD; idx += 256) {
            int k = kt + (idx >> 7);
            sW[idx] = (k < KVALID) ? Wg[k * HD + (idx & 127)] : 0.0f;
        }
        __syncthreads();
        #pragma unroll
        for (int kk = 0; kk < 8; kk++) {
            float4 w = *(const float4*)(sW + kk * HD + lane * 4);
            #pragma unroll
            for (int i = 0; i < 8; i++) {
                float a = fbase[i * sstride + kt + kk];
                acc[i][0] += a * w.x;
                acc[i][1] += a * w.y;
                acc[i][2] += a * w.z;
                acc[i][3] += a * w.w;
            }
        }
    }
}

__global__ __launch_bounds__(256, 1)
void node_kernel(const float* __restrict__ xfeat, const float* __restrict__ T_R,
                 const float* __restrict__ T_t,  const float* __restrict__ u,
                 const int* __restrict__ batch,
                 const float* __restrict__ W3, const float* __restrict__ b3,
                 const float* __restrict__ W4, const float* __restrict__ b4,
                 float* __restrict__ out)
{
    extern __shared__ float sm[];
    float* sG    = sm;
    float* sW    = sG + 64 * GSTR;
    float* sH    = sW + 8 * HD;
    float* sW4   = sH + 64 * NHSTR;
    float* sPose = sW4 + HD * 70;

    int tid = threadIdx.x;
    int n0 = blockIdx.x * 64;

    for (int idx = tid; idx < 64 * HD; idx += 256) {
        int r = idx >> 7, c = idx & 127;
        int n = n0 + r;
        float v = 0.f;
        if (n < NN) v = g_sums[n * HD + c] / fmaxf(g_cnt[n], 1.0f);
        sG[r * GSTR + c] = v;
    }
    for (int idx = tid; idx < 64 * ND; idx += 256) {
        int r = idx >> 6, c = idx & 63;
        int n = n0 + r;
        sG[r * GSTR + HD + c] = (n < NN) ? xfeat[n * ND + c] : 0.f;
    }
    for (int idx = tid; idx < 64 * GD; idx += 256) {
        int r = idx >> 5, c = idx & 31;
        int n = n0 + r;
        sG[r * GSTR + HD + ND + c] = (n < NN) ? u[batch[n] * GD + c] : 0.f;
    }

    int warp = tid >> 5, lane = tid & 31;
    float acc[8][4];
    #pragma unroll
    for (int i = 0; i < 8; i++) { acc[i][0]=0.f; acc[i][1]=0.f; acc[i][2]=0.f; acc[i][3]=0.f; }
    gemm_tile<K3, K3>(sG, GSTR, W3, sW, warp, lane, acc);

    float4 bv = *(const float4*)(b3 + lane * 4);
    #pragma unroll
    for (int i = 0; i < 8; i++) {
        float4 o;
        o.x = fmaxf(acc[i][0] + bv.x, 0.f);
        o.y = fmaxf(acc[i][1] + bv.y, 0.f);
        o.z = fmaxf(acc[i][2] + bv.z, 0.f);
        o.w = fmaxf(acc[i][3] + bv.w, 0.f);
        *(float4*)(sH + (warp * 8 + i) * NHSTR + lane * 4) = o;
    }
    __syncthreads();
    for (int idx = tid; idx < HD * 70; idx += 256) sW4[idx] = W4[idx];
    __syncthreads();

    float a4[8][3];
    #pragma unroll
    for (int i = 0; i < 8; i++) { a4[i][0]=0.f; a4[i][1]=0.f; a4[i][2]=0.f; }
    const float* hb = sH + warp * 8 * NHSTR;
    for (int k = 0; k < HD; k++) {
        float w0 = sW4[k * 70 + lane];
        float w1 = sW4[k * 70 + 32 + lane];
        float w2 = (lane < DOF) ? sW4[k * 70 + 64 + lane] : 0.f;
        #pragma unroll
        for (int i = 0; i < 8; i++) {
            float a = hb[i * NHSTR + k];
            a4[i][0] += a * w0;
            a4[i][1] += a * w1;
            a4[i][2] += a * w2;
        }
    }
    float bb0 = b4[lane], bb1 = b4[32 + lane];
    float bb2 = (lane < DOF) ? b4[64 + lane] : 0.f;
    #pragma unroll
    for (int i = 0; i < 8; i++) {
        int r = warp * 8 + i;
        int n = n0 + r;
        if (n < NN) {
            out[(size_t)n * 77 + lane]      = xfeat[n * ND + lane]      + a4[i][0] + bb0;
            out[(size_t)n * 77 + 32 + lane] = xfeat[n * ND + 32 + lane] + a4[i][1] + bb1;
        }
        if (lane < DOF) sPose[r * DOF + lane] = a4[i][2] + bb2;
    }
    __syncthreads();

    if (tid < 64) {
        int n = n0 + tid;
        if (n < NN) {
            float r0 = sPose[tid*6+0], r1 = sPose[tid*6+1], r2 = sPose[tid*6+2];
            float px = sPose[tid*6+3], py = sPose[tid*6+4], pz = sPose[tid*6+5];
            float nr = sqrtf(px*px + py*py + pz*pz);
            float sc = PI_F * tanhf(nr / PI_F) / (nr + 1e-8f);
            px *= sc; py *= sc; pz *= sc;
            float pp = px*px + py*py + pz*pz;
            float th = sqrtf(pp + 1e-12f);
            float a, b, c;
            if (th < 1e-4f) {
                a = 1.f - pp/6.f; b = 0.5f - pp/24.f; c = 1.f/6.f - pp/120.f;
            } else {
                float s = sinf(th), co = cosf(th);
                a = s / th; b = (1.f - co) / pp; c = (th - s) / (pp * th);
            }
            float Km[9] = {0.f,-pz,py,  pz,0.f,-px,  -py,px,0.f};
            float KK[9] = {px*px-pp, px*py,    px*pz,
                           py*px,    py*py-pp, py*pz,
                           pz*px,    pz*py,    pz*pz-pp};
            float Rd[9], V[9];
            #pragma unroll
            for (int q = 0; q < 9; q++) { Rd[q] = a*Km[q] + b*KK[q]; V[q] = b*Km[q] + c*KK[q]; }
            Rd[0] += 1.f; Rd[4] += 1.f; Rd[8] += 1.f;
            V[0]  += 1.f; V[4]  += 1.f; V[8]  += 1.f;
            float td0 = V[0]*r0 + V[1]*r1 + V[2]*r2;
            float td1 = V[3]*r0 + V[4]*r1 + V[5]*r2;
            float td2 = V[6]*r0 + V[7]*r1 + V[8]*r2;
            float TR[9], Tt[3];
            #pragma unroll
            for (int q = 0; q < 9; q++) TR[q] = T_R[n*9+q];
            #pragma unroll
            for (int q = 0; q < 3; q++) Tt[q] = T_t[n*3+q];
            float* o = out + (size_t)n * 77;
            #pragma unroll
            for (int rr = 0; rr < 3; rr++) {
                #pragma unroll
                for (int cc = 0; cc < 3; cc++) {
                    o[64 + rr*3 + cc] = Rd[rr*3+0]*TR[0+cc] + Rd[rr*3+1]*TR[3+cc] + Rd[rr*3+2]*TR[6+cc];
                }
                o[73 + rr] = Rd[rr*3+0]*Tt[0] + Rd[rr*3+1]*Tt[1] + Rd[rr*3+2]*Tt[2]
                           + (rr == 0 ? td0 : (rr == 1 ? td1 : td2));
            }
            o[76] = sqrtf(pp);
        }
    }
}

extern "C" void kernel_launch(void* const* d_in, const int* in_sizes, int n_in,
                              void* d_out, int out_size) {
    const float* xfeat     = (const float*)d_in[0];
    const float* T_R       = (const float*)d_in[1];
    const float* T_t       = (const float*)d_in[2];
    const float* edge_feat = (const float*)d_in[3];
    const float* TijR      = (const float*)d_in[4];
    const float* Tijt      = (const float*)d_in[5];
    const float* u         = (const float*)d_in[6];
    const int*   ei        = (const int*)d_in[7];
    const int*   batch     = (const int*)d_in[8];
    const float* W1 = (const float*)d_in[9];
    const float* b1 = (const float*)d_in[10];
    const float* W2 = (const float*)d_in[11];
    const float* b2 = (const float*)d_in[12];
    const float* W3 = (const float*)d_in[13];
    const float* b3 = (const float*)d_in[14];
    const float* W4 = (const float*)d_in[15];
    const float* b4 = (const float*)d_in[16];
    float* out = (float*)d_out;

    const int NSMEM = (64 * GSTR + 8 * HD + 64 * NHSTR + HD * 70 + 64 * DOF) * 4;
    cudaFuncSetAttribute(edge_kernel, cudaFuncAttributeMaxDynamicSharedMemorySize, ESMEM);
    cudaFuncSetAttribute(node_kernel, cudaFuncAttributeMaxDynamicSharedMemorySize, NSMEM);

    prep_w<<<(128 * 192 + 128 * 128 + 255) / 256, 256>>>(W1, W2);
    zero_kernel<<<(NN * HD / 4 + 255) / 256, 256>>>();
    edge_kernel<<<EE / EPB, TPB, ESMEM>>>(xfeat, T_R, T_t, edge_feat, TijR, Tijt,
                                          ei, b1, b2);
    node_kernel<<<(NN + 63) / 64, 256, NSMEM>>>(xfeat, T_R, T_t, u, batch,
                                                W3, b3, W4, b4, out);
}

// round 8
// speedup vs baseline: 3.5444x; 1.6591x over previous
#include <cuda_runtime.h>
#include <cuda_bf16.h>
#include <math.h>

#define NN 20000
#define EE 200000
#define ND 64
#define ED 32
#define GD 32
#define HD 128
#define DOF 6
#define PI_F 3.14159265358979f

#define EPB 64
#define RPB 128
#define TPB 512

// edge tiles: pitch 200 els = 400 B (== 16 mod 128 -> ldmatrix conflict-free)
#define SP   200
#define SPB  400
#define IMG  (128 * SPB)      // 51200 B
#define OFF_AH 0
#define OFF_AL IMG
#define OFF_BH (2 * IMG)
#define OFF_BL (3 * IMG)
#define ESMEM  (4 * IMG)      // 204800 B

// node tiles: pitch 264 els = 528 B (== 16 mod 128), K up to 224
#define SP2   264
#define SPB2  528
#define NAIMG (64 * SPB2)     // 33792 B (A: 64 rows)
#define NBIMG (128 * SPB2)    // 67584 B (B: 128 rows)
#define NOFF_AH 0
#define NOFF_AL NAIMG
#define NOFF_BH (2 * NAIMG)
#define NOFF_BL (2 * NAIMG + NBIMG)
#define NSMEM   (2 * NAIMG + 2 * NBIMG)   // 202752 B

static __device__ __align__(16) __nv_bfloat16 gW1h[128 * SP];
static __device__ __align__(16) __nv_bfloat16 gW1l[128 * SP];
static __device__ __align__(16) __nv_bfloat16 gW2h[128 * SP];
static __device__ __align__(16) __nv_bfloat16 gW2l[128 * SP];
static __device__ __align__(16) __nv_bfloat16 gW3h[128 * SP2];
static __device__ __align__(16) __nv_bfloat16 gW3l[128 * SP2];
static __device__ __align__(16) __nv_bfloat16 gW4h[128 * SP2];
static __device__ __align__(16) __nv_bfloat16 gW4l[128 * SP2];

__device__ float g_sums[NN * HD];
__device__ float g_cnt[NN];

__device__ __forceinline__ unsigned smem_u32(const void* p) {
    unsigned a;
    asm("{ .reg .u64 t; cvta.to.shared.u64 t, %1; cvt.u32.u64 %0, t; }" : "=r"(a) : "l"(p));
    return a;
}
__device__ __forceinline__ void split2(float a, float b, unsigned& hi, unsigned& lo) {
    __nv_bfloat16 ha = __float2bfloat16(a), hb = __float2bfloat16(b);
    __nv_bfloat162 th; th.x = ha; th.y = hb;
    hi = *(unsigned*)&th;
    __nv_bfloat162 tl;
    tl.x = __float2bfloat16(a - __bfloat162float(ha));
    tl.y = __float2bfloat16(b - __bfloat162float(hb));
    lo = *(unsigned*)&tl;
}
__device__ __forceinline__ void split4v(float4 v, uint2& hi, uint2& lo) {
    unsigned h0, l0, h1, l1;
    split2(v.x, v.y, h0, l0);
    split2(v.z, v.w, h1, l1);
    hi = make_uint2(h0, h1);
    lo = make_uint2(l0, l1);
}
__device__ __forceinline__ unsigned eoff(int r, int k)  { return (unsigned)(r * SPB  + k * 2); }
__device__ __forceinline__ unsigned eoff2(int r, int k) { return (unsigned)(r * SPB2 + k * 2); }

__device__ __forceinline__ void ldm4(unsigned addr, unsigned* r) {
    asm volatile("ldmatrix.sync.aligned.m8n8.x4.shared.b16 {%0,%1,%2,%3}, [%4];"
        : "=r"(r[0]), "=r"(r[1]), "=r"(r[2]), "=r"(r[3]) : "r"(addr));
}
__device__ __forceinline__ void mma16816(float* d, const unsigned* a, unsigned b0, unsigned b1) {
    asm volatile("mma.sync.aligned.m16n8k16.row.col.f32.bf16.bf16.f32 "
        "{%0,%1,%2,%3}, {%4,%5,%6,%7}, {%8,%9}, {%0,%1,%2,%3};"
        : "+f"(d[0]), "+f"(d[1]), "+f"(d[2]), "+f"(d[3])
        : "r"(a[0]), "r"(a[1]), "r"(a[2]), "r"(a[3]), "r"(b0), "r"(b1));
}

// fused 3-term warp GEMM: d += Ah Bh^T + Al Bh^T + Ah Bl^T over KSTEPS k16-steps
template<int KSTEPS, int PITCHB>
__device__ __forceinline__ void gemm3(unsigned aH, unsigned aL, unsigned bH, unsigned bL,
                                      unsigned aoff0, unsigned boff0, float d[2][4][4]) {
    #pragma unroll
    for (int s = 0; s < KSTEPS; s++) {
        unsigned kb = (unsigned)s * 32u;
        unsigned ah0[4], ah1[4], al0[4], al1[4];
        unsigned bh0[4], bh1[4], bl0[4], bl1[4];
        ldm4(aH + aoff0 + kb, ah0);
        ldm4(aH + aoff0 + 16u * PITCHB + kb, ah1);
        ldm4(aL + aoff0 + kb, al0);
        ldm4(aL + aoff0 + 16u * PITCHB + kb, al1);
        ldm4(bH + boff0 + kb, bh0);
        ldm4(bH + boff0 + 16u * PITCHB + kb, bh1);
        ldm4(bL + boff0 + kb, bl0);
        ldm4(bL + boff0 + 16u * PITCHB + kb, bl1);
        // Ah*Bh
        mma16816(d[0][0], ah0, bh0[0], bh0[1]);
        mma16816(d[0][1], ah0, bh0[2], bh0[3]);
        mma16816(d[0][2], ah0, bh1[0], bh1[1]);
        mma16816(d[0][3], ah0, bh1[2], bh1[3]);
        mma16816(d[1][0], ah1, bh0[0], bh0[1]);
        mma16816(d[1][1], ah1, bh0[2], bh0[3]);
        mma16816(d[1][2], ah1, bh1[0], bh1[1]);
        mma16816(d[1][3], ah1, bh1[2], bh1[3]);
        // Al*Bh
        mma16816(d[0][0], al0, bh0[0], bh0[1]);
        mma16816(d[0][1], al0, bh0[2], bh0[3]);
        mma16816(d[0][2], al0, bh1[0], bh1[1]);
        mma16816(d[0][3], al0, bh1[2], bh1[3]);
        mma16816(d[1][0], al1, bh0[0], bh0[1]);
        mma16816(d[1][1], al1, bh0[2], bh0[3]);
        mma16816(d[1][2], al1, bh1[0], bh1[1]);
        mma16816(d[1][3], al1, bh1[2], bh1[3]);
        // Ah*Bl
        mma16816(d[0][0], ah0, bl0[0], bl0[1]);
        mma16816(d[0][1], ah0, bl0[2], bl0[3]);
        mma16816(d[0][2], ah0, bl1[0], bl1[1]);
        mma16816(d[0][3], ah0, bl1[2], bl1[3]);
        mma16816(d[1][0], ah1, bl0[0], bl0[1]);
        mma16816(d[1][1], ah1, bl0[2], bl0[3]);
        mma16816(d[1][2], ah1, bl1[0], bl1[1]);
        mma16816(d[1][3], ah1, bl1[2], bl1[3]);
    }
}

__global__ void zero_kernel() {
    int idx = blockIdx.x * blockDim.x + threadIdx.x;
    if (idx < NN * HD / 4) ((float4*)g_sums)[idx] = make_float4(0.f, 0.f, 0.f, 0.f);
    if (idx < NN)          g_cnt[idx] = 0.0f;
}

// transpose + bf16-split all weights into pitched [N][K] images
__global__ void prep_w(const float* __restrict__ W1, const float* __restrict__ W2,
                       const float* __restrict__ W3, const float* __restrict__ W4) {
    int idx = blockIdx.x * blockDim.x + threadIdx.x;
    if (idx < 128 * 192) {
        int n = idx / 192, k = idx % 192;
        float w = (k < 172) ? W1[k * HD + n] : 0.f;
        __nv_bfloat16 h = __float2bfloat16(w);
        __nv_bfloat16 l = __float2bfloat16(w - __bfloat162float(h));
        gW1h[n * SP + k] = h; gW1l[n * SP + k] = l;
    } else if (idx < 128 * 192 + 128 * 128) {
        int j = idx - 128 * 192;
        int n = j / 128, k = j % 128;
        float w = W2[k * HD + n];
        __nv_bfloat16 h = __float2bfloat16(w);
        __nv_bfloat16 l = __float2bfloat16(w - __bfloat162float(h));
        gW2h[n * SP + k] = h; gW2l[n * SP + k] = l;
    } else if (idx < 128 * 192 + 128 * 128 + 128 * 224) {
        int j = idx - (128 * 192 + 128 * 128);
        int n = j / 224, k = j % 224;
        float w = W3[k * HD + n];
        __nv_bfloat16 h = __float2bfloat16(w);
        __nv_bfloat16 l = __float2bfloat16(w - __bfloat162float(h));
        gW3h[n * SP2 + k] = h; gW3l[n * SP2 + k] = l;
    } else if (idx < 128 * 192 + 128 * 128 + 128 * 224 + 128 * 128) {
        int j = idx - (128 * 192 + 128 * 128 + 128 * 224);
        int n = j / 128, k = j % 128;
        float w = (n < ND + DOF) ? W4[k * (ND + DOF) + n] : 0.f;
        __nv_bfloat16 h = __float2bfloat16(w);
        __nv_bfloat16 l = __float2bfloat16(w - __bfloat162float(h));
        gW4h[n * SP2 + k] = h; gW4l[n * SP2 + k] = l;
    }
}

// ---------------- Edge kernel: fused 3-term HMMA ----------------
__global__ __launch_bounds__(TPB, 1)
void edge_kernel(const float* __restrict__ xfeat, const float* __restrict__ T_R,
                 const float* __restrict__ T_t,  const float* __restrict__ edge_feat,
                 const float* __restrict__ TijR, const float* __restrict__ Tijt,
                 const int* __restrict__ ei,
                 const float* __restrict__ b1, const float* __restrict__ b2)
{
    extern __shared__ __align__(16) char smraw[];
    char* sAh = smraw + OFF_AH;
    char* sAl = smraw + OFF_AL;
    char* sBh = smraw + OFF_BH;
    char* sBl = smraw + OFF_BL;
    unsigned sb = smem_u32(smraw);

    __shared__ int sNode[RPB];
    __shared__ float sBias1[HD], sBias2[HD];

    int tid = threadIdx.x;
    int warp = tid >> 5, lane = tid & 31;
    int e0 = blockIdx.x * EPB;

    if (tid < HD)          sBias1[tid] = b1[tid];
    else if (tid < 2 * HD) sBias2[tid - HD] = b2[tid - HD];

    {
        const float4* s1 = (const float4*)gW1h;
        const float4* s2 = (const float4*)gW1l;
        float4* d1 = (float4*)sBh;
        float4* d2 = (float4*)sBl;
        for (int i = tid; i < IMG / 16; i += TPB) { d1[i] = s1[i]; d2[i] = s2[i]; }
    }

    {
        int sub = tid & 7;
        int el  = tid >> 3;
        int e   = e0 + el;
        int vi = ei[e], vj = ei[EE + e];
        const float4* xi4 = (const float4*)(xfeat + vi * ND);
        const float4* xj4 = (const float4*)(xfeat + vj * ND);
        const float4* ef4 = (const float4*)(edge_feat + e * ED);
        int rA = el, rB = EPB + el;
        #pragma unroll
        for (int q = sub; q < 16; q += 8) {
            uint2 hi, lo;
            split4v(xi4[q], hi, lo);
            unsigned o1 = eoff(rA, 4 * q), o2 = eoff(rB, 64 + 4 * q);
            *(uint2*)(sAh + o1) = hi; *(uint2*)(sAl + o1) = lo;
            *(uint2*)(sAh + o2) = hi; *(uint2*)(sAl + o2) = lo;
            split4v(xj4[q], hi, lo);
            o1 = eoff(rA, 64 + 4 * q); o2 = eoff(rB, 4 * q);
            *(uint2*)(sAh + o1) = hi; *(uint2*)(sAl + o1) = lo;
            *(uint2*)(sAh + o2) = hi; *(uint2*)(sAl + o2) = lo;
        }
        uint2 hi, lo;
        split4v(ef4[sub], hi, lo);
        unsigned o1 = eoff(rA, 128 + 4 * sub), o2 = eoff(rB, 128 + 4 * sub);
        *(uint2*)(sAh + o1) = hi; *(uint2*)(sAl + o1) = lo;
        *(uint2*)(sAh + o2) = hi; *(uint2*)(sAl + o2) = lo;
    }

    if (tid < EPB) {
        int e = e0 + tid;
        int vi = ei[e], vj = ei[EE + e];
        sNode[tid]       = vj;
        sNode[EPB + tid] = vi;
        float Ri[9], Rj[9], Tr[9], ti[3], tj[3], tt[3];
        #pragma unroll
        for (int k = 0; k < 9; k++) { Ri[k] = T_R[vi*9+k]; Rj[k] = T_R[vj*9+k]; Tr[k] = TijR[e*9+k]; }
        #pragma unroll
        for (int k = 0; k < 3; k++) { ti[k] = T_t[vi*3+k]; tj[k] = T_t[vj*3+k]; tt[k] = Tijt[e*3+k]; }
        float A[9], ta[3];
        #pragma unroll
        for (int r = 0; r < 3; r++)
            #pragma unroll
            for (int c = 0; c < 3; c++)
                A[r*3+c] = Rj[r*3+0]*Ri[c*3+0] + Rj[r*3+1]*Ri[c*3+1] + Rj[r*3+2]*Ri[c*3+2];
        #pragma unroll
        for (int r = 0; r < 3; r++)
            ta[r] = tj[r] - (A[r*3+0]*ti[0] + A[r*3+1]*ti[1] + A[r*3+2]*ti[2]);
        float arrA[12], arrB[12];
        {
            float Re[9], te[3];
            #pragma unroll
            for (int r = 0; r < 3; r++)
                #pragma unroll
                for (int c = 0; c < 3; c++)
                    Re[r*3+c] = A[r*3+0]*Tr[c*3+0] + A[r*3+1]*Tr[c*3+1] + A[r*3+2]*Tr[c*3+2];
            #pragma unroll
            for (int r = 0; r < 3; r++)
                te[r] = ta[r] - (Re[r*3+0]*tt[0] + Re[r*3+1]*tt[1] + Re[r*3+2]*tt[2]);
            arrA[0]=Re[0]; arrA[1]=Re[1]; arrA[2]=Re[2];  arrA[3]=te[0];
            arrA[4]=Re[3]; arrA[5]=Re[4]; arrA[6]=Re[5];  arrA[7]=te[1];
            arrA[8]=Re[6]; arrA[9]=Re[7]; arrA[10]=Re[8]; arrA[11]=te[2];
        }
        {
            float tb[3], Rf[9], tf[3];
            #pragma unroll
            for (int r = 0; r < 3; r++)
                tb[r] = ti[r] - (A[0+r]*tj[0] + A[3+r]*tj[1] + A[6+r]*tj[2]);
            #pragma unroll
            for (int r = 0; r < 3; r++)
                #pragma unroll
                for (int c = 0; c < 3; c++)
                    Rf[r*3+c] = A[0+r]*Tr[0+c] + A[3+r]*Tr[3+c] + A[6+r]*Tr[6+c];
            #pragma unroll
            for (int r = 0; r < 3; r++)
                tf[r] = tb[r] + (A[0+r]*tt[0] + A[3+r]*tt[1] + A[6+r]*tt[2]);
            arrB[0]=Rf[0]; arrB[1]=Rf[1]; arrB[2]=Rf[2];  arrB[3]=tf[0];
            arrB[4]=Rf[3]; arrB[5]=Rf[4]; arrB[6]=Rf[5];  arrB[7]=tf[1];
            arrB[8]=Rf[6]; arrB[9]=Rf[7]; arrB[10]=Rf[8]; arrB[11]=tf[2];
        }
        #pragma unroll
        for (int half = 0; half < 2; half++) {
            int r = half ? (EPB + tid) : tid;
            const float* arr = half ? arrB : arrA;
            #pragma unroll
            for (int m = 0; m < 6; m++) {
                unsigned hi, lo;
                split2(arr[2*m], arr[2*m+1], hi, lo);
                unsigned o = eoff(r, 160 + 2 * m);
                *(unsigned*)(sAh + o) = hi; *(unsigned*)(sAl + o) = lo;
            }
            #pragma unroll
            for (int k = 172; k < 192; k += 2) {
                unsigned o = eoff(r, k);
                *(unsigned*)(sAh + o) = 0u; *(unsigned*)(sAl + o) = 0u;
            }
        }
    }
    __syncthreads();

    const int m_base = (warp & 3) * 32;
    const int n_base = (warp >> 2) * 32;
    unsigned aoff0 = (unsigned)((m_base + (lane & 15)) * SPB + (lane >> 4) * 16);
    unsigned boff0 = (unsigned)((n_base + (lane & 7) + ((lane >> 4) & 1) * 8) * SPB
                                + ((lane >> 3) & 1) * 16);

    float d[2][4][4];
    #pragma unroll
    for (int i = 0; i < 2; i++)
        #pragma unroll
        for (int j = 0; j < 4; j++)
            #pragma unroll
            for (int c = 0; c < 4; c++) d[i][j][c] = 0.f;

    gemm3<12, SPB>(sb + OFF_AH, sb + OFF_AL, sb + OFF_BH, sb + OFF_BL, aoff0, boff0, d);

    __syncthreads();

    {
        const float4* s1 = (const float4*)gW2h;
        const float4* s2 = (const float4*)gW2l;
        float4* d1 = (float4*)sBh;
        float4* d2 = (float4*)sBl;
        for (int i = tid; i < IMG / 16; i += TPB) { d1[i] = s1[i]; d2[i] = s2[i]; }
    }

    {
        int r0b = m_base + (lane >> 2);
        int colb = n_base + 2 * (lane & 3);
        #pragma unroll
        for (int mi = 0; mi < 2; mi++) {
            #pragma unroll
            for (int nb = 0; nb < 4; nb++) {
                int col = colb + nb * 8;
                float bx = sBias1[col], by = sBias1[col + 1];
                int r0 = r0b + mi * 16, r1 = r0 + 8;
                unsigned hi, lo;
                split2(fmaxf(d[mi][nb][0] + bx, 0.f), fmaxf(d[mi][nb][1] + by, 0.f), hi, lo);
                unsigned o = eoff(r0, col);
                *(unsigned*)(sAh + o) = hi; *(unsigned*)(sAl + o) = lo;
                split2(fmaxf(d[mi][nb][2] + bx, 0.f), fmaxf(d[mi][nb][3] + by, 0.f), hi, lo);
                o = eoff(r1, col);
                *(unsigned*)(sAh + o) = hi; *(unsigned*)(sAl + o) = lo;
            }
        }
    }
    __syncthreads();

    #pragma unroll
    for (int i = 0; i < 2; i++)
        #pragma unroll
        for (int j = 0; j < 4; j++)
            #pragma unroll
            for (int c = 0; c < 4; c++) d[i][j][c] = 0.f;

    gemm3<8, SPB>(sb + OFF_AH, sb + OFF_AL, sb + OFF_BH, sb + OFF_BL, aoff0, boff0, d);

    {
        int r0b = m_base + (lane >> 2);
        int colb = n_base + 2 * (lane & 3);
        #pragma unroll
        for (int mi = 0; mi < 2; mi++) {
            int r0 = r0b + mi * 16, r1 = r0 + 8;
            int node0 = sNode[r0], node1 = sNode[r1];
            #pragma unroll
            for (int nb = 0; nb < 4; nb++) {
                int col = colb + nb * 8;
                float bx = sBias2[col], by = sBias2[col + 1];
                float v0 = fmaxf(d[mi][nb][0] + bx, 0.f);
                float v1 = fmaxf(d[mi][nb][1] + by, 0.f);
                float v2 = fmaxf(d[mi][nb][2] + bx, 0.f);
                float v3 = fmaxf(d[mi][nb][3] + by, 0.f);
                float* p0 = g_sums + (size_t)node0 * HD + col;
                float* p1 = g_sums + (size_t)node1 * HD + col;
                asm volatile("red.global.add.v2.f32 [%0], {%1, %2};"
                             :: "l"(p0), "f"(v0), "f"(v1) : "memory");
                asm volatile("red.global.add.v2.f32 [%0], {%1, %2};"
                             :: "l"(p1), "f"(v2), "f"(v3) : "memory");
            }
        }
        if ((warp >> 2) == 0 && (lane & 3) == 0) {
            int rr = lane >> 2;
            atomicAdd(g_cnt + sNode[m_base + rr],      1.0f);
            atomicAdd(g_cnt + sNode[m_base + rr + 8],  1.0f);
            atomicAdd(g_cnt + sNode[m_base + rr + 16], 1.0f);
            atomicAdd(g_cnt + sNode[m_base + rr + 24], 1.0f);
        }
    }
}

// ---------------- Node kernel: fused 3-term HMMA ----------------
__global__ __launch_bounds__(256, 1)
void node_kernel(const float* __restrict__ xfeat, const float* __restrict__ T_R,
                 const float* __restrict__ T_t,  const float* __restrict__ u,
                 const int* __restrict__ batch,
                 const float* __restrict__ b3, const float* __restrict__ b4,
                 float* __restrict__ out)
{
    extern __shared__ __align__(16) char smraw[];
    char* sAh = smraw + NOFF_AH;
    char* sAl = smraw + NOFF_AL;
    char* sBh = smraw + NOFF_BH;
    char* sBl = smraw + NOFF_BL;
    unsigned sb = smem_u32(smraw);

    __shared__ float sBias3[HD], sBias4[ND + DOF];
    __shared__ float sInv[64];
    __shared__ float sPose[64 * DOF];

    int tid = threadIdx.x;
    int warp = tid >> 5, lane = tid & 31;
    int n0 = blockIdx.x * 64;

    if (tid < HD)                 sBias3[tid] = b3[tid];
    else if (tid < HD + ND + DOF) sBias4[tid - HD] = b4[tid - HD];

    if (tid < 64) {
        int n = n0 + tid;
        sInv[tid] = (n < NN) ? 1.0f / fmaxf(g_cnt[n], 1.0f) : 0.f;
    }

    // ---- W3 images -> smem B region ----
    {
        const float4* s1 = (const float4*)gW3h;
        const float4* s2 = (const float4*)gW3l;
        float4* d1 = (float4*)sBh;
        float4* d2 = (float4*)sBl;
        for (int i = tid; i < NBIMG / 16; i += 256) { d1[i] = s1[i]; d2[i] = s2[i]; }
    }
    __syncthreads();   // sInv ready

    // ---- build g = [aggr | xfeat | u[batch]] as bf16 hi/lo ----
    for (int idx = tid; idx < 64 * 112; idx += 256) {
        int r = idx / 112;
        int k = 2 * (idx % 112);
        int n = n0 + r;
        float v0 = 0.f, v1 = 0.f;
        if (n < NN) {
            if (k < HD) {
                float iv = sInv[r];
                v0 = g_sums[(size_t)n * HD + k] * iv;
                v1 = g_sums[(size_t)n * HD + k + 1] * iv;
            } else if (k < HD + ND) {
                v0 = xfeat[(size_t)n * ND + k - HD];
                v1 = xfeat[(size_t)n * ND + k - HD + 1];
            } else {
                int bb = batch[n];
                v0 = u[bb * GD + k - HD - ND];
                v1 = u[bb * GD + k - HD - ND + 1];
            }
        }
        unsigned hi, lo;
        split2(v0, v1, hi, lo);
        unsigned o = eoff2(r, k);
        *(unsigned*)(sAh + o) = hi;
        *(unsigned*)(sAl + o) = lo;
    }
    __syncthreads();

    const int m_base = (warp & 1) * 32;
    const int n_base = (warp >> 1) * 32;
    unsigned aoff0 = (unsigned)((m_base + (lane & 15)) * SPB2 + (lane >> 4) * 16);
    unsigned boff0 = (unsigned)((n_base + (lane & 7) + ((lane >> 4) & 1) * 8) * SPB2
                                + ((lane >> 3) & 1) * 16);

    float d[2][4][4];
    #pragma unroll
    for (int i = 0; i < 2; i++)
        #pragma unroll
        for (int j = 0; j < 4; j++)
            #pragma unroll
            for (int c = 0; c < 4; c++) d[i][j][c] = 0.f;

    // GEMM3: K=224 = 14 k-steps
    gemm3<14, SPB2>(sb + NOFF_AH, sb + NOFF_AL, sb + NOFF_BH, sb + NOFF_BL, aoff0, boff0, d);

    __syncthreads();

    // ---- W4 images -> smem B region ----
    {
        const float4* s1 = (const float4*)gW4h;
        const float4* s2 = (const float4*)gW4l;
        float4* d1 = (float4*)sBh;
        float4* d2 = (float4*)sBl;
        for (int i = tid; i < NBIMG / 16; i += 256) { d1[i] = s1[i]; d2[i] = s2[i]; }
    }

    // ---- epilogue3: bias+relu -> hidden tile in sA ----
    {
        int r0b = m_base + (lane >> 2);
        int colb = n_base + 2 * (lane & 3);
        #pragma unroll
        for (int mi = 0; mi < 2; mi++) {
            #pragma unroll
            for (int nb = 0; nb < 4; nb++) {
                int col = colb + nb * 8;
                float bx = sBias3[col], by = sBias3[col + 1];
                int r0 = r0b + mi * 16, r1 = r0 + 8;
                unsigned hi, lo;
                split2(fmaxf(d[mi][nb][0] + bx, 0.f), fmaxf(d[mi][nb][1] + by, 0.f), hi, lo);
                unsigned o = eoff2(r0, col);
                *(unsigned*)(sAh + o) = hi; *(unsigned*)(sAl + o) = lo;
                split2(fmaxf(d[mi][nb][2] + bx, 0.f), fmaxf(d[mi][nb][3] + by, 0.f), hi, lo);
                o = eoff2(r1, col);
                *(unsigned*)(sAh + o) = hi; *(unsigned*)(sAl + o) = lo;
            }
        }
    }
    __syncthreads();

    #pragma unroll
    for (int i = 0; i < 2; i++)
        #pragma unroll
        for (int j = 0; j < 4; j++)
            #pragma unroll
            for (int c = 0; c < 4; c++) d[i][j][c] = 0.f;

    // GEMM4: K=128 = 8 k-steps (N cols 0..69 valid, rest zero-padded weights)
    gemm3<8, SPB2>(sb + NOFF_AH, sb + NOFF_AL, sb + NOFF_BH, sb + NOFF_BL, aoff0, boff0, d);

    // ---- epilogue4: xupd + pose ----
    {
        int r0b = m_base + (lane >> 2);
        int colb = n_base + 2 * (lane & 3);
        #pragma unroll
        for (int mi = 0; mi < 2; mi++) {
            #pragma unroll
            for (int rr = 0; rr < 2; rr++) {
                int r = r0b + mi * 16 + rr * 8;
                int n = n0 + r;
                #pragma unroll
                for (int nb = 0; nb < 4; nb++) {
                    int col = colb + nb * 8;
                    float v0 = d[mi][nb][rr * 2 + 0];
                    float v1 = d[mi][nb][rr * 2 + 1];
                    if (col < ND) {
                        if (n < NN) {
                            out[(size_t)n * 77 + col]     = xfeat[(size_t)n * ND + col]     + v0 + sBias4[col];
                            out[(size_t)n * 77 + col + 1] = xfeat[(size_t)n * ND + col + 1] + v1 + sBias4[col + 1];
                        }
                    } else if (col < ND + DOF) {
                        sPose[r * DOF + (col - ND)] = v0 + sBias4[col];
                        if (col + 1 < ND + DOF)
                            sPose[r * DOF + (col - ND) + 1] = v1 + sBias4[col + 1];
                    }
                }
            }
        }
    }
    __syncthreads();

    // ---- SE3 epilogue: one thread per node ----
    if (tid < 64) {
        int n = n0 + tid;
        if (n < NN) {
            float r0 = sPose[tid*6+0], r1 = sPose[tid*6+1], r2 = sPose[tid*6+2];
            float px = sPose[tid*6+3], py = sPose[tid*6+4], pz = sPose[tid*6+5];
            float nr = sqrtf(px*px + py*py + pz*pz);
            float sc = PI_F * tanhf(nr / PI_F) / (nr + 1e-8f);
            px *= sc; py *= sc; pz *= sc;
            float pp = px*px + py*py + pz*pz;
            float th = sqrtf(pp + 1e-12f);
            float a, b, c;
            if (th < 1e-4f) {
                a = 1.f - pp/6.f; b = 0.5f - pp/24.f; c = 1.f/6.f - pp/120.f;
            } else {
                float s = sinf(th), co = cosf(th);
                a = s / th; b = (1.f - co) / pp; c = (th - s) / (pp * th);
            }
            float Km[9] = {0.f,-pz,py,  pz,0.f,-px,  -py,px,0.f};
            float KK[9] = {px*px-pp, px*py,    px*pz,
                           py*px,    py*py-pp, py*pz,
                           pz*px,    pz*py,    pz*pz-pp};
            float Rd[9], V[9];
            #pragma unroll
            for (int q = 0; q < 9; q++) { Rd[q] = a*Km[q] + b*KK[q]; V[q] = b*Km[q] + c*KK[q]; }
            Rd[0] += 1.f; Rd[4] += 1.f; Rd[8] += 1.f;
            V[0]  += 1.f; V[4]  += 1.f; V[8]  += 1.f;
            float td0 = V[0]*r0 + V[1]*r1 + V[2]*r2;
            float td1 = V[3]*r0 + V[4]*r1 + V[5]*r2;
            float td2 = V[6]*r0 + V[7]*r1 + V[8]*r2;
            float TR[9], Tt[3];
            #pragma unroll
            for (int q = 0; q < 9; q++) TR[q] = T_R[n*9+q];
            #pragma unroll
            for (int q = 0; q < 3; q++) Tt[q] = T_t[n*3+q];
            float* o = out + (size_t)n * 77;
            #pragma unroll
            for (int rr = 0; rr < 3; rr++) {
                #pragma unroll
                for (int cc = 0; cc < 3; cc++) {
                    o[64 + rr*3 + cc] = Rd[rr*3+0]*TR[0+cc] + Rd[rr*3+1]*TR[3+cc] + Rd[rr*3+2]*TR[6+cc];
                }
                o[73 + rr] = Rd[rr*3+0]*Tt[0] + Rd[rr*3+1]*Tt[1] + Rd[rr*3+2]*Tt[2]
                           + (rr == 0 ? td0 : (rr == 1 ? td1 : td2));
            }
            o[76] = sqrtf(pp);
        }
    }
}

extern "C" void kernel_launch(void* const* d_in, const int* in_sizes, int n_in,
                              void* d_out, int out_size) {
    const float* xfeat     = (const float*)d_in[0];
    const float* T_R       = (const float*)d_in[1];
    const float* T_t       = (const float*)d_in[2];
    const float* edge_feat = (const float*)d_in[3];
    const float* TijR      = (const float*)d_in[4];
    const float* Tijt      = (const float*)d_in[5];
    const float* u         = (const float*)d_in[6];
    const int*   ei        = (const int*)d_in[7];
    const int*   batch     = (const int*)d_in[8];
    const float* W1 = (const float*)d_in[9];
    const float* b1 = (const float*)d_in[10];
    const float* W2 = (const float*)d_in[11];
    const float* b2 = (const float*)d_in[12];
    const float* W3 = (const float*)d_in[13];
    const float* b3 = (const float*)d_in[14];
    const float* W4 = (const float*)d_in[15];
    const float* b4 = (const float*)d_in[16];
    float* out = (float*)d_out;

    cudaFuncSetAttribute(edge_kernel, cudaFuncAttributeMaxDynamicSharedMemorySize, ESMEM);
    cudaFuncSetAttribute(node_kernel, cudaFuncAttributeMaxDynamicSharedMemorySize, NSMEM);

    const int prep_total = 128 * 192 + 128 * 128 + 128 * 224 + 128 * 128;
    prep_w<<<(prep_total + 255) / 256, 256>>>(W1, W2, W3, W4);
    zero_kernel<<<(NN * HD / 4 + 255) / 256, 256>>>();
    edge_kernel<<<EE / EPB, TPB, ESMEM>>>(xfeat, T_R, T_t, edge_feat, TijR, Tijt,
                                          ei, b1, b2);
    node_kernel<<<(NN + 63) / 64, 256, NSMEM>>>(xfeat, T_R, T_t, u, batch,
                                                b3, b4, out);
}

// round 9
// speedup vs baseline: 3.8845x; 1.0960x over previous
#include <cuda_runtime.h>
#include <cuda_bf16.h>
#include <math.h>

#define NN 20000
#define EE 200000
#define ND 64
#define ED 32
#define GD 32
#define HD 128
#define DOF 6
#define PI_F 3.14159265358979f

#define EPB 64
#define RPB 128
#define TPB 512
#define NTPB 512

// edge tiles: pitch 200 els = 400 B (== 16 mod 128 -> ldmatrix conflict-free)
#define SP   200
#define SPB  400
#define IMG  (128 * SPB)      // 51200 B
#define OFF_AH 0
#define OFF_AL IMG
#define OFF_BH (2 * IMG)
#define OFF_BL (3 * IMG)
#define ESMEM  (4 * IMG)      // 204800 B

// node tiles: pitch 264 els = 528 B (== 16 mod 128), K up to 224
#define SP2   264
#define SPB2  528
#define NAIMG (64 * SPB2)     // 33792 B
#define NBIMG (128 * SPB2)    // 67584 B
#define W4ROWS 80
#define NOFF_AH 0
#define NOFF_AL NAIMG
#define NOFF_BH (2 * NAIMG)
#define NOFF_BL (2 * NAIMG + NBIMG)
#define NSMEM   (2 * NAIMG + 2 * NBIMG)   // 202752 B

static __device__ __align__(16) __nv_bfloat16 gW1h[128 * SP];
static __device__ __align__(16) __nv_bfloat16 gW1l[128 * SP];
static __device__ __align__(16) __nv_bfloat16 gW2h[128 * SP];
static __device__ __align__(16) __nv_bfloat16 gW2l[128 * SP];
static __device__ __align__(16) __nv_bfloat16 gW3h[128 * SP2];
static __device__ __align__(16) __nv_bfloat16 gW3l[128 * SP2];
static __device__ __align__(16) __nv_bfloat16 gW4h[128 * SP2];
static __device__ __align__(16) __nv_bfloat16 gW4l[128 * SP2];

__device__ float g_sums[NN * HD];
__device__ float g_cnt[NN];

__device__ __forceinline__ unsigned smem_u32(const void* p) {
    unsigned a;
    asm("{ .reg .u64 t; cvta.to.shared.u64 t, %1; cvt.u32.u64 %0, t; }" : "=r"(a) : "l"(p));
    return a;
}
__device__ __forceinline__ void split2(float a, float b, unsigned& hi, unsigned& lo) {
    __nv_bfloat16 ha = __float2bfloat16(a), hb = __float2bfloat16(b);
    __nv_bfloat162 th; th.x = ha; th.y = hb;
    hi = *(unsigned*)&th;
    __nv_bfloat162 tl;
    tl.x = __float2bfloat16(a - __bfloat162float(ha));
    tl.y = __float2bfloat16(b - __bfloat162float(hb));
    lo = *(unsigned*)&tl;
}
__device__ __forceinline__ void split4v(float4 v, uint2& hi, uint2& lo) {
    unsigned h0, l0, h1, l1;
    split2(v.x, v.y, h0, l0);
    split2(v.z, v.w, h1, l1);
    hi = make_uint2(h0, h1);
    lo = make_uint2(l0, l1);
}
__device__ __forceinline__ unsigned eoff(int r, int k)  { return (unsigned)(r * SPB  + k * 2); }
__device__ __forceinline__ unsigned eoff2(int r, int k) { return (unsigned)(r * SPB2 + k * 2); }

__device__ __forceinline__ void ldm4(unsigned addr, unsigned* r) {
    asm volatile("ldmatrix.sync.aligned.m8n8.x4.shared.b16 {%0,%1,%2,%3}, [%4];"
        : "=r"(r[0]), "=r"(r[1]), "=r"(r[2]), "=r"(r[3]) : "r"(addr));
}
__device__ __forceinline__ void mma16816(float* d, const unsigned* a, unsigned b0, unsigned b1) {
    asm volatile("mma.sync.aligned.m16n8k16.row.col.f32.bf16.bf16.f32 "
        "{%0,%1,%2,%3}, {%4,%5,%6,%7}, {%8,%9}, {%0,%1,%2,%3};"
        : "+f"(d[0]), "+f"(d[1]), "+f"(d[2]), "+f"(d[3])
        : "r"(a[0]), "r"(a[1]), "r"(a[2]), "r"(a[3]), "r"(b0), "r"(b1));
}

// fused 3-term warp GEMM (32x32 tile): d += Ah Bh^T + Al Bh^T + Ah Bl^T
template<int KSTEPS, int PITCHB>
__device__ __forceinline__ void gemm3(unsigned aH, unsigned aL, unsigned bH, unsigned bL,
                                      unsigned aoff0, unsigned boff0, float d[2][4][4]) {
    #pragma unroll
    for (int s = 0; s < KSTEPS; s++) {
        unsigned kb = (unsigned)s * 32u;
        unsigned ah0[4], ah1[4], al0[4], al1[4];
        unsigned bh0[4], bh1[4], bl0[4], bl1[4];
        ldm4(aH + aoff0 + kb, ah0);
        ldm4(aH + aoff0 + 16u * PITCHB + kb, ah1);
        ldm4(aL + aoff0 + kb, al0);
        ldm4(aL + aoff0 + 16u * PITCHB + kb, al1);
        ldm4(bH + boff0 + kb, bh0);
        ldm4(bH + boff0 + 16u * PITCHB + kb, bh1);
        ldm4(bL + boff0 + kb, bl0);
        ldm4(bL + boff0 + 16u * PITCHB + kb, bl1);
        mma16816(d[0][0], ah0, bh0[0], bh0[1]);
        mma16816(d[0][1], ah0, bh0[2], bh0[3]);
        mma16816(d[0][2], ah0, bh1[0], bh1[1]);
        mma16816(d[0][3], ah0, bh1[2], bh1[3]);
        mma16816(d[1][0], ah1, bh0[0], bh0[1]);
        mma16816(d[1][1], ah1, bh0[2], bh0[3]);
        mma16816(d[1][2], ah1, bh1[0], bh1[1]);
        mma16816(d[1][3], ah1, bh1[2], bh1[3]);
        mma16816(d[0][0], al0, bh0[0], bh0[1]);
        mma16816(d[0][1], al0, bh0[2], bh0[3]);
        mma16816(d[0][2], al0, bh1[0], bh1[1]);
        mma16816(d[0][3], al0, bh1[2], bh1[3]);
        mma16816(d[1][0], al1, bh0[0], bh0[1]);
        mma16816(d[1][1], al1, bh0[2], bh0[3]);
        mma16816(d[1][2], al1, bh1[0], bh1[1]);
        mma16816(d[1][3], al1, bh1[2], bh1[3]);
        mma16816(d[0][0], ah0, bl0[0], bl0[1]);
        mma16816(d[0][1], ah0, bl0[2], bl0[3]);
        mma16816(d[0][2], ah0, bl1[0], bl1[1]);
        mma16816(d[0][3], ah0, bl1[2], bl1[3]);
        mma16816(d[1][0], ah1, bl0[0], bl0[1]);
        mma16816(d[1][1], ah1, bl0[2], bl0[3]);
        mma16816(d[1][2], ah1, bl1[0], bl1[1]);
        mma16816(d[1][3], ah1, bl1[2], bl1[3]);
    }
}

// fused 3-term warp GEMM (32x16 tile): for node kernel with 16 warps
template<int KSTEPS, int PITCHB>
__device__ __forceinline__ void gemm3n(unsigned aH, unsigned aL, unsigned bH, unsigned bL,
                                       unsigned aoff0, unsigned boff0, float d[2][2][4]) {
    #pragma unroll
    for (int s = 0; s < KSTEPS; s++) {
        unsigned kb = (unsigned)s * 32u;
        unsigned ah0[4], ah1[4], al0[4], al1[4];
        unsigned bh[4], bl[4];
        ldm4(aH + aoff0 + kb, ah0);
        ldm4(aH + aoff0 + 16u * PITCHB + kb, ah1);
        ldm4(aL + aoff0 + kb, al0);
        ldm4(aL + aoff0 + 16u * PITCHB + kb, al1);
        ldm4(bH + boff0 + kb, bh);
        ldm4(bL + boff0 + kb, bl);
        mma16816(d[0][0], ah0, bh[0], bh[1]);
        mma16816(d[0][1], ah0, bh[2], bh[3]);
        mma16816(d[1][0], ah1, bh[0], bh[1]);
        mma16816(d[1][1], ah1, bh[2], bh[3]);
        mma16816(d[0][0], al0, bh[0], bh[1]);
        mma16816(d[0][1], al0, bh[2], bh[3]);
        mma16816(d[1][0], al1, bh[0], bh[1]);
        mma16816(d[1][1], al1, bh[2], bh[3]);
        mma16816(d[0][0], ah0, bl[0], bl[1]);
        mma16816(d[0][1], ah0, bl[2], bl[3]);
        mma16816(d[1][0], ah1, bl[0], bl[1]);
        mma16816(d[1][1], ah1, bl[2], bl[3]);
    }
}

__global__ void zero_kernel() {
    int idx = blockIdx.x * blockDim.x + threadIdx.x;
    if (idx < NN * HD / 4) ((float4*)g_sums)[idx] = make_float4(0.f, 0.f, 0.f, 0.f);
    if (idx < NN)          g_cnt[idx] = 0.0f;
}

// transpose + bf16-split all weights into pitched [N][K] images
__global__ void prep_w(const float* __restrict__ W1, const float* __restrict__ W2,
                       const float* __restrict__ W3, const float* __restrict__ W4) {
    int idx = blockIdx.x * blockDim.x + threadIdx.x;
    if (idx < 128 * 192) {
        int n = idx / 192, k = idx % 192;
        float w = (k < 172) ? W1[k * HD + n] : 0.f;
        __nv_bfloat16 h = __float2bfloat16(w);
        __nv_bfloat16 l = __float2bfloat16(w - __bfloat162float(h));
        gW1h[n * SP + k] = h; gW1l[n * SP + k] = l;
    } else if (idx < 128 * 192 + 128 * 128) {
        int j = idx - 128 * 192;
        int n = j / 128, k = j % 128;
        float w = W2[k * HD + n];
        __nv_bfloat16 h = __float2bfloat16(w);
        __nv_bfloat16 l = __float2bfloat16(w - __bfloat162float(h));
        gW2h[n * SP + k] = h; gW2l[n * SP + k] = l;
    } else if (idx < 128 * 192 + 128 * 128 + 128 * 224) {
        int j = idx - (128 * 192 + 128 * 128);
        int n = j / 224, k = j % 224;
        float w = W3[k * HD + n];
        __nv_bfloat16 h = __float2bfloat16(w);
        __nv_bfloat16 l = __float2bfloat16(w - __bfloat162float(h));
        gW3h[n * SP2 + k] = h; gW3l[n * SP2 + k] = l;
    } else if (idx < 128 * 192 + 128 * 128 + 128 * 224 + 128 * 128) {
        int j = idx - (128 * 192 + 128 * 128 + 128 * 224);
        int n = j / 128, k = j % 128;
        float w = (n < ND + DOF) ? W4[k * (ND + DOF) + n] : 0.f;
        __nv_bfloat16 h = __float2bfloat16(w);
        __nv_bfloat16 l = __float2bfloat16(w - __bfloat162float(h));
        gW4h[n * SP2 + k] = h; gW4l[n * SP2 + k] = l;
    }
}

// ---------------- Edge kernel: fused 3-term HMMA ----------------
__global__ __launch_bounds__(TPB, 1)
void edge_kernel(const float* __restrict__ xfeat, const float* __restrict__ T_R,
                 const float* __restrict__ T_t,  const float* __restrict__ edge_feat,
                 const float* __restrict__ TijR, const float* __restrict__ Tijt,
                 const int* __restrict__ ei,
                 const float* __restrict__ b1, const float* __restrict__ b2)
{
    extern __shared__ __align__(16) char smraw[];
    char* sAh = smraw + OFF_AH;
    char* sAl = smraw + OFF_AL;
    char* sBh = smraw + OFF_BH;
    char* sBl = smraw + OFF_BL;
    unsigned sb = smem_u32(smraw);

    __shared__ int sNode[RPB];
    __shared__ float sBias1[HD], sBias2[HD];

    int tid = threadIdx.x;
    int warp = tid >> 5, lane = tid & 31;
    int e0 = blockIdx.x * EPB;

    if (tid < HD)          sBias1[tid] = b1[tid];
    else if (tid < 2 * HD) sBias2[tid - HD] = b2[tid - HD];

    {
        const float4* s1 = (const float4*)gW1h;
        const float4* s2 = (const float4*)gW1l;
        float4* d1 = (float4*)sBh;
        float4* d2 = (float4*)sBl;
        for (int i = tid; i < IMG / 16; i += TPB) { d1[i] = s1[i]; d2[i] = s2[i]; }
    }

    {
        int sub = tid & 7;
        int el  = tid >> 3;
        int e   = e0 + el;
        int vi = ei[e], vj = ei[EE + e];
        const float4* xi4 = (const float4*)(xfeat + vi * ND);
        const float4* xj4 = (const float4*)(xfeat + vj * ND);
        const float4* ef4 = (const float4*)(edge_feat + e * ED);
        int rA = el, rB = EPB + el;
        #pragma unroll
        for (int q = sub; q < 16; q += 8) {
            uint2 hi, lo;
            split4v(xi4[q], hi, lo);
            unsigned o1 = eoff(rA, 4 * q), o2 = eoff(rB, 64 + 4 * q);
            *(uint2*)(sAh + o1) = hi; *(uint2*)(sAl + o1) = lo;
            *(uint2*)(sAh + o2) = hi; *(uint2*)(sAl + o2) = lo;
            split4v(xj4[q], hi, lo);
            o1 = eoff(rA, 64 + 4 * q); o2 = eoff(rB, 4 * q);
            *(uint2*)(sAh + o1) = hi; *(uint2*)(sAl + o1) = lo;
            *(uint2*)(sAh + o2) = hi; *(uint2*)(sAl + o2) = lo;
        }
        uint2 hi, lo;
        split4v(ef4[sub], hi, lo);
        unsigned o1 = eoff(rA, 128 + 4 * sub), o2 = eoff(rB, 128 + 4 * sub);
        *(uint2*)(sAh + o1) = hi; *(uint2*)(sAl + o1) = lo;
        *(uint2*)(sAh + o2) = hi; *(uint2*)(sAl + o2) = lo;
    }

    if (tid < EPB) {
        int e = e0 + tid;
        int vi = ei[e], vj = ei[EE + e];
        sNode[tid]       = vj;
        sNode[EPB + tid] = vi;
        float Ri[9], Rj[9], Tr[9], ti[3], tj[3], tt[3];
        #pragma unroll
        for (int k = 0; k < 9; k++) { Ri[k] = T_R[vi*9+k]; Rj[k] = T_R[vj*9+k]; Tr[k] = TijR[e*9+k]; }
        #pragma unroll
        for (int k = 0; k < 3; k++) { ti[k] = T_t[vi*3+k]; tj[k] = T_t[vj*3+k]; tt[k] = Tijt[e*3+k]; }
        float A[9], ta[3];
        #pragma unroll
        for (int r = 0; r < 3; r++)
            #pragma unroll
            for (int c = 0; c < 3; c++)
                A[r*3+c] = Rj[r*3+0]*Ri[c*3+0] + Rj[r*3+1]*Ri[c*3+1] + Rj[r*3+2]*Ri[c*3+2];
        #pragma unroll
        for (int r = 0; r < 3; r++)
            ta[r] = tj[r] - (A[r*3+0]*ti[0] + A[r*3+1]*ti[1] + A[r*3+2]*ti[2]);
        float arrA[12], arrB[12];
        {
            float Re[9], te[3];
            #pragma unroll
            for (int r = 0; r < 3; r++)
                #pragma unroll
                for (int c = 0; c < 3; c++)
                    Re[r*3+c] = A[r*3+0]*Tr[c*3+0] + A[r*3+1]*Tr[c*3+1] + A[r*3+2]*Tr[c*3+2];
            #pragma unroll
            for (int r = 0; r < 3; r++)
                te[r] = ta[r] - (Re[r*3+0]*tt[0] + Re[r*3+1]*tt[1] + Re[r*3+2]*tt[2]);
            arrA[0]=Re[0]; arrA[1]=Re[1]; arrA[2]=Re[2];  arrA[3]=te[0];
            arrA[4]=Re[3]; arrA[5]=Re[4]; arrA[6]=Re[5];  arrA[7]=te[1];
            arrA[8]=Re[6]; arrA[9]=Re[7]; arrA[10]=Re[8]; arrA[11]=te[2];
        }
        {
            float tb[3], Rf[9], tf[3];
            #pragma unroll
            for (int r = 0; r < 3; r++)
                tb[r] = ti[r] - (A[0+r]*tj[0] + A[3+r]*tj[1] + A[6+r]*tj[2]);
            #pragma unroll
            for (int r = 0; r < 3; r++)
                #pragma unroll
                for (int c = 0; c < 3; c++)
                    Rf[r*3+c] = A[0+r]*Tr[0+c] + A[3+r]*Tr[3+c] + A[6+r]*Tr[6+c];
            #pragma unroll
            for (int r = 0; r < 3; r++)
                tf[r] = tb[r] + (A[0+r]*tt[0] + A[3+r]*tt[1] + A[6+r]*tt[2]);
            arrB[0]=Rf[0]; arrB[1]=Rf[1]; arrB[2]=Rf[2];  arrB[3]=tf[0];
            arrB[4]=Rf[3]; arrB[5]=Rf[4]; arrB[6]=Rf[5];  arrB[7]=tf[1];
            arrB[8]=Rf[6]; arrB[9]=Rf[7]; arrB[10]=Rf[8]; arrB[11]=tf[2];
        }
        #pragma unroll
        for (int half = 0; half < 2; half++) {
            int r = half ? (EPB + tid) : tid;
            const float* arr = half ? arrB : arrA;
            #pragma unroll
            for (int m = 0; m < 6; m++) {
                unsigned hi, lo;
                split2(arr[2*m], arr[2*m+1], hi, lo);
                unsigned o = eoff(r, 160 + 2 * m);
                *(unsigned*)(sAh + o) = hi; *(unsigned*)(sAl + o) = lo;
            }
            #pragma unroll
            for (int k = 172; k < 176; k += 2) {
                unsigned o = eoff(r, k);
                *(unsigned*)(sAh + o) = 0u; *(unsigned*)(sAl + o) = 0u;
            }
        }
    }
    __syncthreads();

    const int m_base = (warp & 3) * 32;
    const int n_base = (warp >> 2) * 32;
    unsigned aoff0 = (unsigned)((m_base + (lane & 15)) * SPB + (lane >> 4) * 16);
    unsigned boff0 = (unsigned)((n_base + (lane & 7) + ((lane >> 4) & 1) * 8) * SPB
                                + ((lane >> 3) & 1) * 16);

    float d[2][4][4];
    #pragma unroll
    for (int i = 0; i < 2; i++)
        #pragma unroll
        for (int j = 0; j < 4; j++)
            #pragma unroll
            for (int c = 0; c < 4; c++) d[i][j][c] = 0.f;

    // GEMM1: K=176 (172 + pad) = 11 k-steps
    gemm3<11, SPB>(sb + OFF_AH, sb + OFF_AL, sb + OFF_BH, sb + OFF_BL, aoff0, boff0, d);

    __syncthreads();

    {
        const float4* s1 = (const float4*)gW2h;
        const float4* s2 = (const float4*)gW2l;
        float4* d1 = (float4*)sBh;
        float4* d2 = (float4*)sBl;
        for (int i = tid; i < IMG / 16; i += TPB) { d1[i] = s1[i]; d2[i] = s2[i]; }
    }

    {
        int r0b = m_base + (lane >> 2);
        int colb = n_base + 2 * (lane & 3);
        #pragma unroll
        for (int mi = 0; mi < 2; mi++) {
            #pragma unroll
            for (int nb = 0; nb < 4; nb++) {
                int col = colb + nb * 8;
                float bx = sBias1[col], by = sBias1[col + 1];
                int r0 = r0b + mi * 16, r1 = r0 + 8;
                unsigned hi, lo;
                split2(fmaxf(d[mi][nb][0] + bx, 0.f), fmaxf(d[mi][nb][1] + by, 0.f), hi, lo);
                unsigned o = eoff(r0, col);
                *(unsigned*)(sAh + o) = hi; *(unsigned*)(sAl + o) = lo;
                split2(fmaxf(d[mi][nb][2] + bx, 0.f), fmaxf(d[mi][nb][3] + by, 0.f), hi, lo);
                o = eoff(r1, col);
                *(unsigned*)(sAh + o) = hi; *(unsigned*)(sAl + o) = lo;
            }
        }
    }
    __syncthreads();

    #pragma unroll
    for (int i = 0; i < 2; i++)
        #pragma unroll
        for (int j = 0; j < 4; j++)
            #pragma unroll
            for (int c = 0; c < 4; c++) d[i][j][c] = 0.f;

    gemm3<8, SPB>(sb + OFF_AH, sb + OFF_AL, sb + OFF_BH, sb + OFF_BL, aoff0, boff0, d);

    {
        int r0b = m_base + (lane >> 2);
        int colb = n_base + 2 * (lane & 3);
        #pragma unroll
        for (int mi = 0; mi < 2; mi++) {
            int r0 = r0b + mi * 16, r1 = r0 + 8;
            int node0 = sNode[r0], node1 = sNode[r1];
            #pragma unroll
            for (int nb = 0; nb < 4; nb++) {
                int col = colb + nb * 8;
                float bx = sBias2[col], by = sBias2[col + 1];
                float v0 = fmaxf(d[mi][nb][0] + bx, 0.f);
                float v1 = fmaxf(d[mi][nb][1] + by, 0.f);
                float v2 = fmaxf(d[mi][nb][2] + bx, 0.f);
                float v3 = fmaxf(d[mi][nb][3] + by, 0.f);
                float* p0 = g_sums + (size_t)node0 * HD + col;
                float* p1 = g_sums + (size_t)node1 * HD + col;
                asm volatile("red.global.add.v2.f32 [%0], {%1, %2};"
                             :: "l"(p0), "f"(v0), "f"(v1) : "memory");
                asm volatile("red.global.add.v2.f32 [%0], {%1, %2};"
                             :: "l"(p1), "f"(v2), "f"(v3) : "memory");
            }
        }
        if ((warp >> 2) == 0 && (lane & 3) == 0) {
            int rr = lane >> 2;
            atomicAdd(g_cnt + sNode[m_base + rr],      1.0f);
            atomicAdd(g_cnt + sNode[m_base + rr + 8],  1.0f);
            atomicAdd(g_cnt + sNode[m_base + rr + 16], 1.0f);
            atomicAdd(g_cnt + sNode[m_base + rr + 24], 1.0f);
        }
    }
}

// ---------------- Node kernel: fused 3-term HMMA, 16 warps ----------------
__global__ __launch_bounds__(NTPB, 1)
void node_kernel(const float* __restrict__ xfeat, const float* __restrict__ T_R,
                 const float* __restrict__ T_t,  const float* __restrict__ u,
                 const int* __restrict__ batch,
                 const float* __restrict__ b3, const float* __restrict__ b4,
                 float* __restrict__ out)
{
    extern __shared__ __align__(16) char smraw[];
    char* sAh = smraw + NOFF_AH;
    char* sAl = smraw + NOFF_AL;
    char* sBh = smraw + NOFF_BH;
    char* sBl = smraw + NOFF_BL;
    unsigned sb = smem_u32(smraw);

    __shared__ float sBias3[HD], sBias4[ND + DOF];
    __shared__ float sInv[64];
    __shared__ float sPose[64 * DOF];

    int tid = threadIdx.x;
    int warp = tid >> 5, lane = tid & 31;
    int n0 = blockIdx.x * 64;

    if (tid < HD)                 sBias3[tid] = b3[tid];
    else if (tid < HD + ND + DOF) sBias4[tid - HD] = b4[tid - HD];

    if (tid >= 256 && tid < 320) {
        int r = tid - 256;
        int n = n0 + r;
        sInv[r] = (n < NN) ? 1.0f / fmaxf(g_cnt[n], 1.0f) : 0.f;
    }

    // ---- W3 images -> smem B region ----
    {
        const float4* s1 = (const float4*)gW3h;
        const float4* s2 = (const float4*)gW3l;
        float4* d1 = (float4*)sBh;
        float4* d2 = (float4*)sBl;
        for (int i = tid; i < NBIMG / 16; i += NTPB) { d1[i] = s1[i]; d2[i] = s2[i]; }
    }
    __syncthreads();   // sInv ready

    // ---- build g = [aggr | xfeat | u[batch]] as bf16 hi/lo ----
    for (int idx = tid; idx < 64 * 112; idx += NTPB) {
        int r = idx / 112;
        int k = 2 * (idx % 112);
        int n = n0 + r;
        float v0 = 0.f, v1 = 0.f;
        if (n < NN) {
            if (k < HD) {
                float iv = sInv[r];
                v0 = g_sums[(size_t)n * HD + k] * iv;
                v1 = g_sums[(size_t)n * HD + k + 1] * iv;
            } else if (k < HD + ND) {
                v0 = xfeat[(size_t)n * ND + k - HD];
                v1 = xfeat[(size_t)n * ND + k - HD + 1];
            } else {
                int bb = batch[n];
                v0 = u[bb * GD + k - HD - ND];
                v1 = u[bb * GD + k - HD - ND + 1];
            }
        }
        unsigned hi, lo;
        split2(v0, v1, hi, lo);
        unsigned o = eoff2(r, k);
        *(unsigned*)(sAh + o) = hi;
        *(unsigned*)(sAl + o) = lo;
    }
    __syncthreads();

    // 16 warps: m 2 x n 8, warp tile 32x16
    const int m_base = (warp & 1) * 32;
    const int n_base = (warp >> 1) * 16;
    unsigned aoff0 = (unsigned)((m_base + (lane & 15)) * SPB2 + (lane >> 4) * 16);
    unsigned boff0 = (unsigned)((n_base + (lane & 7) + ((lane >> 4) & 1) * 8) * SPB2
                                + ((lane >> 3) & 1) * 16);

    float d[2][2][4];
    #pragma unroll
    for (int i = 0; i < 2; i++)
        #pragma unroll
        for (int j = 0; j < 2; j++)
            #pragma unroll
            for (int c = 0; c < 4; c++) d[i][j][c] = 0.f;

    // GEMM3: K=224 = 14 k-steps
    gemm3n<14, SPB2>(sb + NOFF_AH, sb + NOFF_AL, sb + NOFF_BH, sb + NOFF_BL, aoff0, boff0, d);

    __syncthreads();

    // ---- W4 images (only first 80 N rows) -> smem B region ----
    {
        const float4* s1 = (const float4*)gW4h;
        const float4* s2 = (const float4*)gW4l;
        float4* d1 = (float4*)sBh;
        float4* d2 = (float4*)sBl;
        for (int i = tid; i < (W4ROWS * SPB2) / 16; i += NTPB) { d1[i] = s1[i]; d2[i] = s2[i]; }
    }

    // ---- epilogue3: bias+relu -> hidden tile in sA ----
    {
        int r0b = m_base + (lane >> 2);
        int colb = n_base + 2 * (lane & 3);
        #pragma unroll
        for (int mi = 0; mi < 2; mi++) {
            #pragma unroll
            for (int nb = 0; nb < 2; nb++) {
                int col = colb + nb * 8;
                float bx = sBias3[col], by = sBias3[col + 1];
                int r0 = r0b + mi * 16, r1 = r0 + 8;
                unsigned hi, lo;
                split2(fmaxf(d[mi][nb][0] + bx, 0.f), fmaxf(d[mi][nb][1] + by, 0.f), hi, lo);
                unsigned o = eoff2(r0, col);
                *(unsigned*)(sAh + o) = hi; *(unsigned*)(sAl + o) = lo;
                split2(fmaxf(d[mi][nb][2] + bx, 0.f), fmaxf(d[mi][nb][3] + by, 0.f), hi, lo);
                o = eoff2(r1, col);
                *(unsigned*)(sAh + o) = hi; *(unsigned*)(sAl + o) = lo;
            }
        }
    }
    __syncthreads();

    #pragma unroll
    for (int i = 0; i < 2; i++)
        #pragma unroll
        for (int j = 0; j < 2; j++)
            #pragma unroll
            for (int c = 0; c < 4; c++) d[i][j][c] = 0.f;

    // GEMM4: K=128 = 8 k-steps, N=80 valid -> warps with n_base >= 80 idle
    if (n_base < W4ROWS) {
        gemm3n<8, SPB2>(sb + NOFF_AH, sb + NOFF_AL, sb + NOFF_BH, sb + NOFF_BL, aoff0, boff0, d);

        int r0b = m_base + (lane >> 2);
        int colb = n_base + 2 * (lane & 3);
        #pragma unroll
        for (int mi = 0; mi < 2; mi++) {
            #pragma unroll
            for (int rr = 0; rr < 2; rr++) {
                int r = r0b + mi * 16 + rr * 8;
                int n = n0 + r;
                #pragma unroll
                for (int nb = 0; nb < 2; nb++) {
                    int col = colb + nb * 8;
                    float v0 = d[mi][nb][rr * 2 + 0];
                    float v1 = d[mi][nb][rr * 2 + 1];
                    if (col < ND) {
                        if (n < NN) {
                            out[(size_t)n * 77 + col]     = xfeat[(size_t)n * ND + col]     + v0 + sBias4[col];
                            out[(size_t)n * 77 + col + 1] = xfeat[(size_t)n * ND + col + 1] + v1 + sBias4[col + 1];
                        }
                    } else if (col < ND + DOF) {
                        sPose[r * DOF + (col - ND)] = v0 + sBias4[col];
                        if (col + 1 < ND + DOF)
                            sPose[r * DOF + (col - ND) + 1] = v1 + sBias4[col + 1];
                    }
                }
            }
        }
    }
    __syncthreads();

    // ---- SE3 epilogue: one thread per node ----
    if (tid < 64) {
        int n = n0 + tid;
        if (n < NN) {
            float r0 = sPose[tid*6+0], r1 = sPose[tid*6+1], r2 = sPose[tid*6+2];
            float px = sPose[tid*6+3], py = sPose[tid*6+4], pz = sPose[tid*6+5];
            float nr = sqrtf(px*px + py*py + pz*pz);
            float sc = PI_F * tanhf(nr / PI_F) / (nr + 1e-8f);
            px *= sc; py *= sc; pz *= sc;
            float pp = px*px + py*py + pz*pz;
            float th = sqrtf(pp + 1e-12f);
            float a, b, c;
            if (th < 1e-4f) {
                a = 1.f - pp/6.f; b = 0.5f - pp/24.f; c = 1.f/6.f - pp/120.f;
            } else {
                float s = sinf(th), co = cosf(th);
                a = s / th; b = (1.f - co) / pp; c = (th - s) / (pp * th);
            }
            float Km[9] = {0.f,-pz,py,  pz,0.f,-px,  -py,px,0.f};
            float KK[9] = {px*px-pp, px*py,    px*pz,
                           py*px,    py*py-pp, py*pz,
                           pz*px,    pz*py,    pz*pz-pp};
            float Rd[9], V[9];
            #pragma unroll
            for (int q = 0; q < 9; q++) { Rd[q] = a*Km[q] + b*KK[q]; V[q] = b*Km[q] + c*KK[q]; }
            Rd[0] += 1.f; Rd[4] += 1.f; Rd[8] += 1.f;
            V[0]  += 1.f; V[4]  += 1.f; V[8]  += 1.f;
            float td0 = V[0]*r0 + V[1]*r1 + V[2]*r2;
            float td1 = V[3]*r0 + V[4]*r1 + V[5]*r2;
            float td2 = V[6]*r0 + V[7]*r1 + V[8]*r2;
            float TR[9], Tt[3];
            #pragma unroll
            for (int q = 0; q < 9; q++) TR[q] = T_R[n*9+q];
            #pragma unroll
            for (int q = 0; q < 3; q++) Tt[q] = T_t[n*3+q];
            float* o = out + (size_t)n * 77;
            #pragma unroll
            for (int rr = 0; rr < 3; rr++) {
                #pragma unroll
                for (int cc = 0; cc < 3; cc++) {
                    o[64 + rr*3 + cc] = Rd[rr*3+0]*TR[0+cc] + Rd[rr*3+1]*TR[3+cc] + Rd[rr*3+2]*TR[6+cc];
                }
                o[73 + rr] = Rd[rr*3+0]*Tt[0] + Rd[rr*3+1]*Tt[1] + Rd[rr*3+2]*Tt[2]
                           + (rr == 0 ? td0 : (rr == 1 ? td1 : td2));
            }
            o[76] = sqrtf(pp);
        }
    }
}

extern "C" void kernel_launch(void* const* d_in, const int* in_sizes, int n_in,
                              void* d_out, int out_size) {
    const float* xfeat     = (const float*)d_in[0];
    const float* T_R       = (const float*)d_in[1];
    const float* T_t       = (const float*)d_in[2];
    const float* edge_feat = (const float*)d_in[3];
    const float* TijR      = (const float*)d_in[4];
    const float* Tijt      = (const float*)d_in[5];
    const float* u         = (const float*)d_in[6];
    const int*   ei        = (const int*)d_in[7];
    const int*   batch     = (const int*)d_in[8];
    const float* W1 = (const float*)d_in[9];
    const float* b1 = (const float*)d_in[10];
    const float* W2 = (const float*)d_in[11];
    const float* b2 = (const float*)d_in[12];
    const float* W3 = (const float*)d_in[13];
    const float* b3 = (const float*)d_in[14];
    const float* W4 = (const float*)d_in[15];
    const float* b4 = (const float*)d_in[16];
    float* out = (float*)d_out;

    cudaFuncSetAttribute(edge_kernel, cudaFuncAttributeMaxDynamicSharedMemorySize, ESMEM);
    cudaFuncSetAttribute(node_kernel, cudaFuncAttributeMaxDynamicSharedMemorySize, NSMEM);

    const int prep_total = 128 * 192 + 128 * 128 + 128 * 224 + 128 * 128;
    prep_w<<<(prep_total + 255) / 256, 256>>>(W1, W2, W3, W4);
    zero_kernel<<<(NN * HD / 4 + 255) / 256, 256>>>();
    edge_kernel<<<EE / EPB, TPB, ESMEM>>>(xfeat, T_R, T_t, edge_feat, TijR, Tijt,
                                          ei, b1, b2);
    node_kernel<<<(NN + 63) / 64, NTPB, NSMEM>>>(xfeat, T_R, T_t, u, batch,
                                                 b3, b4, out);
}

// round 10
// speedup vs baseline: 4.1491x; 1.0681x over previous
#include <cuda_runtime.h>
#include <cuda_bf16.h>
#include <math.h>

#define NN 20000
#define EE 200000
#define ND 64
#define ED 32
#define GD 32
#define HD 128
#define DOF 6
#define PI_F 3.14159265358979f

#define EPB 32     // edges per edge-block
#define RPB 64     // rows per edge-block
#define TPB 256    // threads per edge-block
#define NTPB 512

// A tiles: pitch 200 els = 400 B (== 16 mod 128 -> ldmatrix conflict-free)
#define SP   200
#define SPB  400
#define EAIMG (RPB * SPB)     // 25600 B per A image
// streamed W chunk: 128 N-rows x 32 K-els, row pitch 80 B (8 rows distinct mod 128)
#define ECH_P   80
#define ECH_IMG 10240         // 128 * 80
#define ECH_ELS 5120          // bf16 els per chunk image
// edge smem layout
#define OFF_AH 0
#define OFF_AL EAIMG
#define B0H (2 * EAIMG)           // 51200
#define B0L (B0H + ECH_IMG)       // 61440
#define B1H (B0L + ECH_IMG)       // 71680
#define B1L (B1H + ECH_IMG)       // 81920
#define ESMEM (B1L + ECH_IMG)     // 92160

// node tiles: pitch 264 els = 528 B, K up to 224
#define SP2   264
#define SPB2  528
#define NAIMG (64 * SPB2)
#define NBIMG (128 * SPB2)
#define W4ROWS 80
#define NOFF_AH 0
#define NOFF_AL NAIMG
#define NOFF_BH (2 * NAIMG)
#define NOFF_BL (2 * NAIMG + NBIMG)
#define NSMEM   (2 * NAIMG + 2 * NBIMG)

// chunked W1/W2 images (6 / 4 chunks)
static __device__ __align__(16) __nv_bfloat16 gW1ch[6 * ECH_ELS];
static __device__ __align__(16) __nv_bfloat16 gW1cl[6 * ECH_ELS];
static __device__ __align__(16) __nv_bfloat16 gW2ch[4 * ECH_ELS];
static __device__ __align__(16) __nv_bfloat16 gW2cl[4 * ECH_ELS];
static __device__ __align__(16) __nv_bfloat16 gW3h[128 * SP2];
static __device__ __align__(16) __nv_bfloat16 gW3l[128 * SP2];
static __device__ __align__(16) __nv_bfloat16 gW4h[128 * SP2];
static __device__ __align__(16) __nv_bfloat16 gW4l[128 * SP2];

__device__ float g_sums[NN * HD];
__device__ float g_cnt[NN];

__device__ __forceinline__ unsigned smem_u32(const void* p) {
    unsigned a;
    asm("{ .reg .u64 t; cvta.to.shared.u64 t, %1; cvt.u32.u64 %0, t; }" : "=r"(a) : "l"(p));
    return a;
}
__device__ __forceinline__ void split2(float a, float b, unsigned& hi, unsigned& lo) {
    __nv_bfloat16 ha = __float2bfloat16(a), hb = __float2bfloat16(b);
    __nv_bfloat162 th; th.x = ha; th.y = hb;
    hi = *(unsigned*)&th;
    __nv_bfloat162 tl;
    tl.x = __float2bfloat16(a - __bfloat162float(ha));
    tl.y = __float2bfloat16(b - __bfloat162float(hb));
    lo = *(unsigned*)&tl;
}
__device__ __forceinline__ void split4v(float4 v, uint2& hi, uint2& lo) {
    unsigned h0, l0, h1, l1;
    split2(v.x, v.y, h0, l0);
    split2(v.z, v.w, h1, l1);
    hi = make_uint2(h0, h1);
    lo = make_uint2(l0, l1);
}
__device__ __forceinline__ unsigned eoff(int r, int k)  { return (unsigned)(r * SPB  + k * 2); }
__device__ __forceinline__ unsigned eoff2(int r, int k) { return (unsigned)(r * SPB2 + k * 2); }

__device__ __forceinline__ void ldm4(unsigned addr, unsigned* r) {
    asm volatile("ldmatrix.sync.aligned.m8n8.x4.shared.b16 {%0,%1,%2,%3}, [%4];"
        : "=r"(r[0]), "=r"(r[1]), "=r"(r[2]), "=r"(r[3]) : "r"(addr));
}
__device__ __forceinline__ void mma16816(float* d, const unsigned* a, unsigned b0, unsigned b1) {
    asm volatile("mma.sync.aligned.m16n8k16.row.col.f32.bf16.bf16.f32 "
        "{%0,%1,%2,%3}, {%4,%5,%6,%7}, {%8,%9}, {%0,%1,%2,%3};"
        : "+f"(d[0]), "+f"(d[1]), "+f"(d[2]), "+f"(d[3])
        : "r"(a[0]), "r"(a[1]), "r"(a[2]), "r"(a[3]), "r"(b0), "r"(b1));
}

// ---- streamed-chunk helpers (edge kernel) ----
__device__ __forceinline__ void ldg_chunk(const uint2* gh, const uint2* gl, int c, int tid,
                                          uint2 rh[5], uint2 rl[5]) {
    const uint2* ph = gh + c * (ECH_IMG / 8) + tid;
    const uint2* pl = gl + c * (ECH_IMG / 8) + tid;
    #pragma unroll
    for (int i = 0; i < 5; i++) { rh[i] = ph[i * 256]; rl[i] = pl[i * 256]; }
}
__device__ __forceinline__ void sts_chunk(char* bh, char* bl, int tid,
                                          const uint2 rh[5], const uint2 rl[5]) {
    uint2* dh = (uint2*)bh + tid;
    uint2* dl = (uint2*)bl + tid;
    #pragma unroll
    for (int i = 0; i < 5; i++) { dh[i * 256] = rh[i]; dl[i * 256] = rl[i]; }
}

// 3-term MMA over one K32 chunk (warp tile 32x32)
__device__ __forceinline__ void mma_chunk(unsigned aH, unsigned aL, unsigned bH, unsigned bL,
                                          unsigned aoffc, unsigned boff0, int steps,
                                          float d[2][4][4]) {
    for (int s = 0; s < steps; s++) {
        unsigned ka = aoffc + (unsigned)s * 32u;
        unsigned kb = boff0 + (unsigned)s * 32u;
        unsigned ah0[4], ah1[4], al0[4], al1[4];
        unsigned bh0[4], bh1[4], bl0[4], bl1[4];
        ldm4(aH + ka, ah0);
        ldm4(aH + ka + 16u * SPB, ah1);
        ldm4(aL + ka, al0);
        ldm4(aL + ka + 16u * SPB, al1);
        ldm4(bH + kb, bh0);
        ldm4(bH + kb + 16u * ECH_P, bh1);
        ldm4(bL + kb, bl0);
        ldm4(bL + kb + 16u * ECH_P, bl1);
        mma16816(d[0][0], ah0, bh0[0], bh0[1]);
        mma16816(d[0][1], ah0, bh0[2], bh0[3]);
        mma16816(d[0][2], ah0, bh1[0], bh1[1]);
        mma16816(d[0][3], ah0, bh1[2], bh1[3]);
        mma16816(d[1][0], ah1, bh0[0], bh0[1]);
        mma16816(d[1][1], ah1, bh0[2], bh0[3]);
        mma16816(d[1][2], ah1, bh1[0], bh1[1]);
        mma16816(d[1][3], ah1, bh1[2], bh1[3]);
        mma16816(d[0][0], al0, bh0[0], bh0[1]);
        mma16816(d[0][1], al0, bh0[2], bh0[3]);
        mma16816(d[0][2], al0, bh1[0], bh1[1]);
        mma16816(d[0][3], al0, bh1[2], bh1[3]);
        mma16816(d[1][0], al1, bh0[0], bh0[1]);
        mma16816(d[1][1], al1, bh0[2], bh0[3]);
        mma16816(d[1][2], al1, bh1[0], bh1[1]);
        mma16816(d[1][3], al1, bh1[2], bh1[3]);
        mma16816(d[0][0], ah0, bl0[0], bl0[1]);
        mma16816(d[0][1], ah0, bl0[2], bl0[3]);
        mma16816(d[0][2], ah0, bl1[0], bl1[1]);
        mma16816(d[0][3], ah0, bl1[2], bl1[3]);
        mma16816(d[1][0], ah1, bl0[0], bl0[1]);
        mma16816(d[1][1], ah1, bl0[2], bl0[3]);
        mma16816(d[1][2], ah1, bl1[0], bl1[1]);
        mma16816(d[1][3], ah1, bl1[2], bl1[3]);
    }
}

// double-buffered streamed GEMM: NCH chunks, last chunk has LAST k16-steps
template<int NCH, int LAST>
__device__ __forceinline__ void gemm_stream(const __nv_bfloat16* gWh, const __nv_bfloat16* gWl,
                                            char* smraw, unsigned sb,
                                            unsigned aoff0, unsigned boff0, int tid,
                                            float d[2][4][4]) {
    const uint2* gh = (const uint2*)gWh;
    const uint2* gl = (const uint2*)gWl;
    uint2 rh[5], rl[5];
    ldg_chunk(gh, gl, 0, tid, rh, rl);
    sts_chunk(smraw + B0H, smraw + B0L, tid, rh, rl);
    if (NCH > 1) ldg_chunk(gh, gl, 1, tid, rh, rl);
    __syncthreads();
    #pragma unroll
    for (int c = 0; c < NCH; c++) {
        unsigned bH = sb + ((c & 1) ? B1H : B0H);
        unsigned bL = bH + ECH_IMG;
        int steps = (c == NCH - 1) ? LAST : 2;
        mma_chunk(sb + OFF_AH, sb + OFF_AL, bH, bL, aoff0 + (unsigned)c * 64u, boff0, steps, d);
        if (c + 1 < NCH)
            sts_chunk(smraw + (((c + 1) & 1) ? B1H : B0H),
                      smraw + (((c + 1) & 1) ? B1L : B0L), tid, rh, rl);
        if (c + 2 < NCH) ldg_chunk(gh, gl, c + 2, tid, rh, rl);
        __syncthreads();
    }
}

// node-kernel 3-term warp GEMM (32x16 tile)
template<int KSTEPS, int PITCHB>
__device__ __forceinline__ void gemm3n(unsigned aH, unsigned aL, unsigned bH, unsigned bL,
                                       unsigned aoff0, unsigned boff0, float d[2][2][4]) {
    #pragma unroll
    for (int s = 0; s < KSTEPS; s++) {
        unsigned kb = (unsigned)s * 32u;
        unsigned ah0[4], ah1[4], al0[4], al1[4];
        unsigned bh[4], bl[4];
        ldm4(aH + aoff0 + kb, ah0);
        ldm4(aH + aoff0 + 16u * PITCHB + kb, ah1);
        ldm4(aL + aoff0 + kb, al0);
        ldm4(aL + aoff0 + 16u * PITCHB + kb, al1);
        ldm4(bH + boff0 + kb, bh);
        ldm4(bL + boff0 + kb, bl);
        mma16816(d[0][0], ah0, bh[0], bh[1]);
        mma16816(d[0][1], ah0, bh[2], bh[3]);
        mma16816(d[1][0], ah1, bh[0], bh[1]);
        mma16816(d[1][1], ah1, bh[2], bh[3]);
        mma16816(d[0][0], al0, bh[0], bh[1]);
        mma16816(d[0][1], al0, bh[2], bh[3]);
        mma16816(d[1][0], al1, bh[0], bh[1]);
        mma16816(d[1][1], al1, bh[2], bh[3]);
        mma16816(d[0][0], ah0, bl[0], bl[1]);
        mma16816(d[0][1], ah0, bl[2], bl[3]);
        mma16816(d[1][0], ah1, bl[0], bl[1]);
        mma16816(d[1][1], ah1, bl[2], bl[3]);
    }
}

__global__ void zero_kernel() {
    int idx = blockIdx.x * blockDim.x + threadIdx.x;
    if (idx < NN * HD / 4) ((float4*)g_sums)[idx] = make_float4(0.f, 0.f, 0.f, 0.f);
    if (idx < NN)          g_cnt[idx] = 0.0f;
}

// prep: W1/W2 -> chunked images; W3/W4 -> pitched images
__global__ void prep_w(const float* __restrict__ W1, const float* __restrict__ W2,
                       const float* __restrict__ W3, const float* __restrict__ W4) {
    int idx = blockIdx.x * blockDim.x + threadIdx.x;
    const int NW1 = 6 * ECH_ELS;            // 30720
    const int NW2 = 4 * ECH_ELS;            // 20480
    if (idx < NW1) {
        int c = idx / ECH_ELS;
        int rem = idx % ECH_ELS;
        int n = rem / 40, kk = rem % 40;
        int k = c * 32 + kk;
        float w = (kk < 32 && k < 172) ? W1[k * HD + n] : 0.f;
        __nv_bfloat16 h = __float2bfloat16(w);
        __nv_bfloat16 l = __float2bfloat16(w - __bfloat162float(h));
        gW1ch[idx] = h; gW1cl[idx] = l;
    } else if (idx < NW1 + NW2) {
        int j = idx - NW1;
        int c = j / ECH_ELS;
        int rem = j % ECH_ELS;
        int n = rem / 40, kk = rem % 40;
        int k = c * 32 + kk;
        float w = (kk < 32) ? W2[k * HD + n] : 0.f;
        __nv_bfloat16 h = __float2bfloat16(w);
        __nv_bfloat16 l = __float2bfloat16(w - __bfloat162float(h));
        gW2ch[j] = h; gW2cl[j] = l;
    } else if (idx < NW1 + NW2 + 128 * 224) {
        int j = idx - (NW1 + NW2);
        int n = j / 224, k = j % 224;
        float w = W3[k * HD + n];
        __nv_bfloat16 h = __float2bfloat16(w);
        __nv_bfloat16 l = __float2bfloat16(w - __bfloat162float(h));
        gW3h[n * SP2 + k] = h; gW3l[n * SP2 + k] = l;
    } else if (idx < NW1 + NW2 + 128 * 224 + 128 * 128) {
        int j = idx - (NW1 + NW2 + 128 * 224);
        int n = j / 128, k = j % 128;
        float w = (n < ND + DOF) ? W4[k * (ND + DOF) + n] : 0.f;
        __nv_bfloat16 h = __float2bfloat16(w);
        __nv_bfloat16 l = __float2bfloat16(w - __bfloat162float(h));
        gW4h[n * SP2 + k] = h; gW4l[n * SP2 + k] = l;
    }
}

// ---------------- Edge kernel: 32 edges, streamed W, 2 blocks/SM ----------------
__global__ __launch_bounds__(TPB, 2)
void edge_kernel(const float* __restrict__ xfeat, const float* __restrict__ T_R,
                 const float* __restrict__ T_t,  const float* __restrict__ edge_feat,
                 const float* __restrict__ TijR, const float* __restrict__ Tijt,
                 const int* __restrict__ ei,
                 const float* __restrict__ b1, const float* __restrict__ b2)
{
    extern __shared__ __align__(16) char smraw[];
    char* sAh = smraw + OFF_AH;
    char* sAl = smraw + OFF_AL;
    unsigned sb = smem_u32(smraw);

    __shared__ int sNode[RPB];
    __shared__ float sBias1[HD], sBias2[HD];

    int tid = threadIdx.x;
    int warp = tid >> 5, lane = tid & 31;
    int e0 = blockIdx.x * EPB;

    if (tid < HD)          sBias1[tid] = b1[tid];
    else if (tid < 2 * HD) sBias2[tid - HD] = b2[tid - HD];

    // ---- feature build: bf16 hi/lo pitched rows (8 threads per edge) ----
    {
        int sub = tid & 7;
        int el  = tid >> 3;              // 0..31
        int e   = e0 + el;
        int vi = ei[e], vj = ei[EE + e];
        const float4* xi4 = (const float4*)(xfeat + vi * ND);
        const float4* xj4 = (const float4*)(xfeat + vj * ND);
        const float4* ef4 = (const float4*)(edge_feat + e * ED);
        int rA = el, rB = EPB + el;
        #pragma unroll
        for (int q = sub; q < 16; q += 8) {
            uint2 hi, lo;
            split4v(xi4[q], hi, lo);
            unsigned o1 = eoff(rA, 4 * q), o2 = eoff(rB, 64 + 4 * q);
            *(uint2*)(sAh + o1) = hi; *(uint2*)(sAl + o1) = lo;
            *(uint2*)(sAh + o2) = hi; *(uint2*)(sAl + o2) = lo;
            split4v(xj4[q], hi, lo);
            o1 = eoff(rA, 64 + 4 * q); o2 = eoff(rB, 4 * q);
            *(uint2*)(sAh + o1) = hi; *(uint2*)(sAl + o1) = lo;
            *(uint2*)(sAh + o2) = hi; *(uint2*)(sAl + o2) = lo;
        }
        uint2 hi, lo;
        split4v(ef4[sub], hi, lo);
        unsigned o1 = eoff(rA, 128 + 4 * sub), o2 = eoff(rB, 128 + 4 * sub);
        *(uint2*)(sAh + o1) = hi; *(uint2*)(sAl + o1) = lo;
        *(uint2*)(sAh + o2) = hi; *(uint2*)(sAl + o2) = lo;
    }

    // ---- relative pose (1 thread per edge) + K padding to 176 ----
    if (tid < EPB) {
        int e = e0 + tid;
        int vi = ei[e], vj = ei[EE + e];
        sNode[tid]       = vj;
        sNode[EPB + tid] = vi;
        float Ri[9], Rj[9], Tr[9], ti[3], tj[3], tt[3];
        #pragma unroll
        for (int k = 0; k < 9; k++) { Ri[k] = T_R[vi*9+k]; Rj[k] = T_R[vj*9+k]; Tr[k] = TijR[e*9+k]; }
        #pragma unroll
        for (int k = 0; k < 3; k++) { ti[k] = T_t[vi*3+k]; tj[k] = T_t[vj*3+k]; tt[k] = Tijt[e*3+k]; }
        float A[9], ta[3];
        #pragma unroll
        for (int r = 0; r < 3; r++)
            #pragma unroll
            for (int c = 0; c < 3; c++)
                A[r*3+c] = Rj[r*3+0]*Ri[c*3+0] + Rj[r*3+1]*Ri[c*3+1] + Rj[r*3+2]*Ri[c*3+2];
        #pragma unroll
        for (int r = 0; r < 3; r++)
            ta[r] = tj[r] - (A[r*3+0]*ti[0] + A[r*3+1]*ti[1] + A[r*3+2]*ti[2]);
        float arrA[12], arrB[12];
        {
            float Re[9], te[3];
            #pragma unroll
            for (int r = 0; r < 3; r++)
                #pragma unroll
                for (int c = 0; c < 3; c++)
                    Re[r*3+c] = A[r*3+0]*Tr[c*3+0] + A[r*3+1]*Tr[c*3+1] + A[r*3+2]*Tr[c*3+2];
            #pragma unroll
            for (int r = 0; r < 3; r++)
                te[r] = ta[r] - (Re[r*3+0]*tt[0] + Re[r*3+1]*tt[1] + Re[r*3+2]*tt[2]);
            arrA[0]=Re[0]; arrA[1]=Re[1]; arrA[2]=Re[2];  arrA[3]=te[0];
            arrA[4]=Re[3]; arrA[5]=Re[4]; arrA[6]=Re[5];  arrA[7]=te[1];
            arrA[8]=Re[6]; arrA[9]=Re[7]; arrA[10]=Re[8]; arrA[11]=te[2];
        }
        {
            float tb[3], Rf[9], tf[3];
            #pragma unroll
            for (int r = 0; r < 3; r++)
                tb[r] = ti[r] - (A[0+r]*tj[0] + A[3+r]*tj[1] + A[6+r]*tj[2]);
            #pragma unroll
            for (int r = 0; r < 3; r++)
                #pragma unroll
                for (int c = 0; c < 3; c++)
                    Rf[r*3+c] = A[0+r]*Tr[0+c] + A[3+r]*Tr[3+c] + A[6+r]*Tr[6+c];
            #pragma unroll
            for (int r = 0; r < 3; r++)
                tf[r] = tb[r] + (A[0+r]*tt[0] + A[3+r]*tt[1] + A[6+r]*tt[2]);
            arrB[0]=Rf[0]; arrB[1]=Rf[1]; arrB[2]=Rf[2];  arrB[3]=tf[0];
            arrB[4]=Rf[3]; arrB[5]=Rf[4]; arrB[6]=Rf[5];  arrB[7]=tf[1];
            arrB[8]=Rf[6]; arrB[9]=Rf[7]; arrB[10]=Rf[8]; arrB[11]=tf[2];
        }
        #pragma unroll
        for (int half = 0; half < 2; half++) {
            int r = half ? (EPB + tid) : tid;
            const float* arr = half ? arrB : arrA;
            #pragma unroll
            for (int m = 0; m < 6; m++) {
                unsigned hi, lo;
                split2(arr[2*m], arr[2*m+1], hi, lo);
                unsigned o = eoff(r, 160 + 2 * m);
                *(unsigned*)(sAh + o) = hi; *(unsigned*)(sAl + o) = lo;
            }
            #pragma unroll
            for (int k = 172; k < 176; k += 2) {
                unsigned o = eoff(r, k);
                *(unsigned*)(sAh + o) = 0u; *(unsigned*)(sAl + o) = 0u;
            }
        }
    }
    // NOTE: gemm_stream's first __syncthreads() orders the build before MMA.

    // warp tiling: 2 m-tiles x 4 n-tiles of 32x32
    const int m_base = (warp & 1) * 32;
    const int n_base = (warp >> 1) * 32;
    unsigned aoff0 = (unsigned)((m_base + (lane & 15)) * SPB + (lane >> 4) * 16);
    unsigned boff0 = (unsigned)((n_base + (lane & 7) + ((lane >> 4) & 1) * 8) * ECH_P
                                + ((lane >> 3) & 1) * 16);

    float d[2][4][4];
    #pragma unroll
    for (int i = 0; i < 2; i++)
        #pragma unroll
        for (int j = 0; j < 4; j++)
            #pragma unroll
            for (int c = 0; c < 4; c++) d[i][j][c] = 0.f;

    // GEMM1: 6 chunks (last has 1 k16-step) -> K = 176
    gemm_stream<6, 1>(gW1ch, gW1cl, smraw, sb, aoff0, boff0, tid, d);

    // epilogue1: bias+relu -> hidden bf16 hi/lo back into A region
    {
        int r0b = m_base + (lane >> 2);
        int colb = n_base + 2 * (lane & 3);
        #pragma unroll
        for (int mi = 0; mi < 2; mi++) {
            #pragma unroll
            for (int nb = 0; nb < 4; nb++) {
                int col = colb + nb * 8;
                float bx = sBias1[col], by = sBias1[col + 1];
                int r0 = r0b + mi * 16, r1 = r0 + 8;
                unsigned hi, lo;
                split2(fmaxf(d[mi][nb][0] + bx, 0.f), fmaxf(d[mi][nb][1] + by, 0.f), hi, lo);
                unsigned o = eoff(r0, col);
                *(unsigned*)(sAh + o) = hi; *(unsigned*)(sAl + o) = lo;
                split2(fmaxf(d[mi][nb][2] + bx, 0.f), fmaxf(d[mi][nb][3] + by, 0.f), hi, lo);
                o = eoff(r1, col);
                *(unsigned*)(sAh + o) = hi; *(unsigned*)(sAl + o) = lo;
            }
        }
    }
    __syncthreads();   // H tile complete before GEMM2 reads it

    #pragma unroll
    for (int i = 0; i < 2; i++)
        #pragma unroll
        for (int j = 0; j < 4; j++)
            #pragma unroll
            for (int c = 0; c < 4; c++) d[i][j][c] = 0.f;

    // GEMM2: 4 chunks -> K = 128
    gemm_stream<4, 2>(gW2ch, gW2cl, smraw, sb, aoff0, boff0, tid, d);

    // epilogue2: bias+relu -> red.v2 scatter into g_sums
    {
        int r0b = m_base + (lane >> 2);
        int colb = n_base + 2 * (lane & 3);
        #pragma unroll
        for (int mi = 0; mi < 2; mi++) {
            int r0 = r0b + mi * 16, r1 = r0 + 8;
            int node0 = sNode[r0], node1 = sNode[r1];
            #pragma unroll
            for (int nb = 0; nb < 4; nb++) {
                int col = colb + nb * 8;
                float bx = sBias2[col], by = sBias2[col + 1];
                float v0 = fmaxf(d[mi][nb][0] + bx, 0.f);
                float v1 = fmaxf(d[mi][nb][1] + by, 0.f);
                float v2 = fmaxf(d[mi][nb][2] + bx, 0.f);
                float v3 = fmaxf(d[mi][nb][3] + by, 0.f);
                float* p0 = g_sums + (size_t)node0 * HD + col;
                float* p1 = g_sums + (size_t)node1 * HD + col;
                asm volatile("red.global.add.v2.f32 [%0], {%1, %2};"
                             :: "l"(p0), "f"(v0), "f"(v1) : "memory");
                asm volatile("red.global.add.v2.f32 [%0], {%1, %2};"
                             :: "l"(p1), "f"(v2), "f"(v3) : "memory");
            }
        }
        if ((warp >> 1) == 0 && (lane & 3) == 0) {
            int rr = lane >> 2;
            atomicAdd(g_cnt + sNode[m_base + rr],      1.0f);
            atomicAdd(g_cnt + sNode[m_base + rr + 8],  1.0f);
            atomicAdd(g_cnt + sNode[m_base + rr + 16], 1.0f);
            atomicAdd(g_cnt + sNode[m_base + rr + 24], 1.0f);
        }
    }
}

// ---------------- Node kernel: fused 3-term HMMA, 16 warps ----------------
__global__ __launch_bounds__(NTPB, 1)
void node_kernel(const float* __restrict__ xfeat, const float* __restrict__ T_R,
                 const float* __restrict__ T_t,  const float* __restrict__ u,
                 const int* __restrict__ batch,
                 const float* __restrict__ b3, const float* __restrict__ b4,
                 float* __restrict__ out)
{
    extern __shared__ __align__(16) char smraw[];
    char* sAh = smraw + NOFF_AH;
    char* sAl = smraw + NOFF_AL;
    char* sBh = smraw + NOFF_BH;
    char* sBl = smraw + NOFF_BL;
    unsigned sb = smem_u32(smraw);

    __shared__ float sBias3[HD], sBias4[ND + DOF];
    __shared__ float sInv[64];
    __shared__ float sPose[64 * DOF];

    int tid = threadIdx.x;
    int warp = tid >> 5, lane = tid & 31;
    int n0 = blockIdx.x * 64;

    if (tid < HD)                 sBias3[tid] = b3[tid];
    else if (tid < HD + ND + DOF) sBias4[tid - HD] = b4[tid - HD];

    if (tid >= 256 && tid < 320) {
        int r = tid - 256;
        int n = n0 + r;
        sInv[r] = (n < NN) ? 1.0f / fmaxf(g_cnt[n], 1.0f) : 0.f;
    }

    {
        const float4* s1 = (const float4*)gW3h;
        const float4* s2 = (const float4*)gW3l;
        float4* d1 = (float4*)sBh;
        float4* d2 = (float4*)sBl;
        for (int i = tid; i < NBIMG / 16; i += NTPB) { d1[i] = s1[i]; d2[i] = s2[i]; }
    }
    __syncthreads();

    for (int idx = tid; idx < 64 * 112; idx += NTPB) {
        int r = idx / 112;
        int k = 2 * (idx % 112);
        int n = n0 + r;
        float v0 = 0.f, v1 = 0.f;
        if (n < NN) {
            if (k < HD) {
                float iv = sInv[r];
                v0 = g_sums[(size_t)n * HD + k] * iv;
                v1 = g_sums[(size_t)n * HD + k + 1] * iv;
            } else if (k < HD + ND) {
                v0 = xfeat[(size_t)n * ND + k - HD];
                v1 = xfeat[(size_t)n * ND + k - HD + 1];
            } else {
                int bb = batch[n];
                v0 = u[bb * GD + k - HD - ND];
                v1 = u[bb * GD + k - HD - ND + 1];
            }
        }
        unsigned hi, lo;
        split2(v0, v1, hi, lo);
        unsigned o = eoff2(r, k);
        *(unsigned*)(sAh + o) = hi;
        *(unsigned*)(sAl + o) = lo;
    }
    __syncthreads();

    const int m_base = (warp & 1) * 32;
    const int n_base = (warp >> 1) * 16;
    unsigned aoff0 = (unsigned)((m_base + (lane & 15)) * SPB2 + (lane >> 4) * 16);
    unsigned boff0 = (unsigned)((n_base + (lane & 7) + ((lane >> 4) & 1) * 8) * SPB2
                                + ((lane >> 3) & 1) * 16);

    float d[2][2][4];
    #pragma unroll
    for (int i = 0; i < 2; i++)
        #pragma unroll
        for (int j = 0; j < 2; j++)
            #pragma unroll
            for (int c = 0; c < 4; c++) d[i][j][c] = 0.f;

    gemm3n<14, SPB2>(sb + NOFF_AH, sb + NOFF_AL, sb + NOFF_BH, sb + NOFF_BL, aoff0, boff0, d);

    __syncthreads();

    {
        const float4* s1 = (const float4*)gW4h;
        const float4* s2 = (const float4*)gW4l;
        float4* d1 = (float4*)sBh;
        float4* d2 = (float4*)sBl;
        for (int i = tid; i < (W4ROWS * SPB2) / 16; i += NTPB) { d1[i] = s1[i]; d2[i] = s2[i]; }
    }

    {
        int r0b = m_base + (lane >> 2);
        int colb = n_base + 2 * (lane & 3);
        #pragma unroll
        for (int mi = 0; mi < 2; mi++) {
            #pragma unroll
            for (int nb = 0; nb < 2; nb++) {
                int col = colb + nb * 8;
                float bx = sBias3[col], by = sBias3[col + 1];
                int r0 = r0b + mi * 16, r1 = r0 + 8;
                unsigned hi, lo;
                split2(fmaxf(d[mi][nb][0] + bx, 0.f), fmaxf(d[mi][nb][1] + by, 0.f), hi, lo);
                unsigned o = eoff2(r0, col);
                *(unsigned*)(sAh + o) = hi; *(unsigned*)(sAl + o) = lo;
                split2(fmaxf(d[mi][nb][2] + bx, 0.f), fmaxf(d[mi][nb][3] + by, 0.f), hi, lo);
                o = eoff2(r1, col);
                *(unsigned*)(sAh + o) = hi; *(unsigned*)(sAl + o) = lo;
            }
        }
    }
    __syncthreads();

    #pragma unroll
    for (int i = 0; i < 2; i++)
        #pragma unroll
        for (int j = 0; j < 2; j++)
            #pragma unroll
            for (int c = 0; c < 4; c++) d[i][j][c] = 0.f;

    if (n_base < W4ROWS) {
        gemm3n<8, SPB2>(sb + NOFF_AH, sb + NOFF_AL, sb + NOFF_BH, sb + NOFF_BL, aoff0, boff0, d);

        int r0b = m_base + (lane >> 2);
        int colb = n_base + 2 * (lane & 3);
        #pragma unroll
        for (int mi = 0; mi < 2; mi++) {
            #pragma unroll
            for (int rr = 0; rr < 2; rr++) {
                int r = r0b + mi * 16 + rr * 8;
                int n = n0 + r;
                #pragma unroll
                for (int nb = 0; nb < 2; nb++) {
                    int col = colb + nb * 8;
                    float v0 = d[mi][nb][rr * 2 + 0];
                    float v1 = d[mi][nb][rr * 2 + 1];
                    if (col < ND) {
                        if (n < NN) {
                            out[(size_t)n * 77 + col]     = xfeat[(size_t)n * ND + col]     + v0 + sBias4[col];
                            out[(size_t)n * 77 + col + 1] = xfeat[(size_t)n * ND + col + 1] + v1 + sBias4[col + 1];
                        }
                    } else if (col < ND + DOF) {
                        sPose[r * DOF + (col - ND)] = v0 + sBias4[col];
                        if (col + 1 < ND + DOF)
                            sPose[r * DOF + (col - ND) + 1] = v1 + sBias4[col + 1];
                    }
                }
            }
        }
    }
    __syncthreads();

    if (tid < 64) {
        int n = n0 + tid;
        if (n < NN) {
            float r0 = sPose[tid*6+0], r1 = sPose[tid*6+1], r2 = sPose[tid*6+2];
            float px = sPose[tid*6+3], py = sPose[tid*6+4], pz = sPose[tid*6+5];
            float nr = sqrtf(px*px + py*py + pz*pz);
            float sc = PI_F * tanhf(nr / PI_F) / (nr + 1e-8f);
            px *= sc; py *= sc; pz *= sc;
            float pp = px*px + py*py + pz*pz;
            float th = sqrtf(pp + 1e-12f);
            float a, b, c;
            if (th < 1e-4f) {
                a = 1.f - pp/6.f; b = 0.5f - pp/24.f; c = 1.f/6.f - pp/120.f;
            } else {
                float s = sinf(th), co = cosf(th);
                a = s / th; b = (1.f - co) / pp; c = (th - s) / (pp * th);
            }
            float Km[9] = {0.f,-pz,py,  pz,0.f,-px,  -py,px,0.f};
            float KK[9] = {px*px-pp, px*py,    px*pz,
                           py*px,    py*py-pp, py*pz,
                           pz*px,    pz*py,    pz*pz-pp};
            float Rd[9], V[9];
            #pragma unroll
            for (int q = 0; q < 9; q++) { Rd[q] = a*Km[q] + b*KK[q]; V[q] = b*Km[q] + c*KK[q]; }
            Rd[0] += 1.f; Rd[4] += 1.f; Rd[8] += 1.f;
            V[0]  += 1.f; V[4]  += 1.f; V[8]  += 1.f;
            float td0 = V[0]*r0 + V[1]*r1 + V[2]*r2;
            float td1 = V[3]*r0 + V[4]*r1 + V[5]*r2;
            float td2 = V[6]*r0 + V[7]*r1 + V[8]*r2;
            float TR[9], Tt[3];
            #pragma unroll
            for (int q = 0; q < 9; q++) TR[q] = T_R[n*9+q];
            #pragma unroll
            for (int q = 0; q < 3; q++) Tt[q] = T_t[n*3+q];
            float* o = out + (size_t)n * 77;
            #pragma unroll
            for (int rr = 0; rr < 3; rr++) {
                #pragma unroll
                for (int cc = 0; cc < 3; cc++) {
                    o[64 + rr*3 + cc] = Rd[rr*3+0]*TR[0+cc] + Rd[rr*3+1]*TR[3+cc] + Rd[rr*3+2]*TR[6+cc];
                }
                o[73 + rr] = Rd[rr*3+0]*Tt[0] + Rd[rr*3+1]*Tt[1] + Rd[rr*3+2]*Tt[2]
                           + (rr == 0 ? td0 : (rr == 1 ? td1 : td2));
            }
            o[76] = sqrtf(pp);
        }
    }
}

extern "C" void kernel_launch(void* const* d_in, const int* in_sizes, int n_in,
                              void* d_out, int out_size) {
    const float* xfeat     = (const float*)d_in[0];
    const float* T_R       = (const float*)d_in[1];
    const float* T_t       = (const float*)d_in[2];
    const float* edge_feat = (const float*)d_in[3];
    const float* TijR      = (const float*)d_in[4];
    const float* Tijt      = (const float*)d_in[5];
    const float* u         = (const float*)d_in[6];
    const int*   ei        = (const int*)d_in[7];
    const int*   batch     = (const int*)d_in[8];
    const float* W1 = (const float*)d_in[9];
    const float* b1 = (const float*)d_in[10];
    const float* W2 = (const float*)d_in[11];
    const float* b2 = (const float*)d_in[12];
    const float* W3 = (const float*)d_in[13];
    const float* b3 = (const float*)d_in[14];
    const float* W4 = (const float*)d_in[15];
    const float* b4 = (const float*)d_in[16];
    float* out = (float*)d_out;

    cudaFuncSetAttribute(edge_kernel, cudaFuncAttributeMaxDynamicSharedMemorySize, ESMEM);
    cudaFuncSetAttribute(node_kernel, cudaFuncAttributeMaxDynamicSharedMemorySize, NSMEM);

    const int prep_total = 6 * ECH_ELS + 4 * ECH_ELS + 128 * 224 + 128 * 128;
    prep_w<<<(prep_total + 255) / 256, 256>>>(W1, W2, W3, W4);
    zero_kernel<<<(NN * HD / 4 + 255) / 256, 256>>>();
    edge_kernel<<<EE / EPB, TPB, ESMEM>>>(xfeat, T_R, T_t, edge_feat, TijR, Tijt,
                                          ei, b1, b2);
    node_kernel<<<(NN + 63) / 64, NTPB, NSMEM>>>(xfeat, T_R, T_t, u, batch,
                                                 b3, b4, out);
}